// round 3
// baseline (speedup 1.0000x reference)
#include <cuda_runtime.h>
#include <math.h>

// ---------------------------------------------------------------------------
// R-NEM cell: fused GEMM(+bias+act+LayerNorm[+attention]) kernels, fp32 SIMT.
//
// Pipeline:
//   s1   = LN(relu(state @ enc_W + b))                       [16384 x 250]
//   core = LN(relu(concat(fs,cs) @ core_W + b))              [114688 x 250]
//   ctx  = LN(relu(core @ ctx_W + b))                        [114688 x 250]
//   att  = sigmoid(LN(tanh(core @ att_W1 + b1)) @ att_W2+b2) [114688]
//   eff  = sum_j ctx[bk,j,:] * att[bk,j]                     [16384 x 250]
//   out  = concat(s1, eff, x) @ out_W + out_b                [16384 x 250]
// ---------------------------------------------------------------------------

#define EPS_LN 1e-5f

static constexpr int Bn  = 2048;
static constexpr int Kn  = 8;
static constexpr int BK  = Bn * Kn;          // 16384 entity rows
static constexpr int RR  = BK * (Kn - 1);    // 114688 pair rows
static constexpr int H1  = 250;
static constexpr int Mx  = 576;
static constexpr int HAn = 100;

// Scratch (device globals: allocation-free per harness rules)
__device__ float g_s1  [BK * H1];   // 16.4 MB
__device__ float g_core[RR * H1];   // 114.7 MB
__device__ float g_ctx [RR * H1];   // 114.7 MB
__device__ float g_att [RR];        // 0.46 MB
__device__ float g_eff [BK * H1];   // 16.4 MB

__device__ __forceinline__ float warp_sum(float v) {
    v += __shfl_xor_sync(0xffffffffu, v, 16);
    v += __shfl_xor_sync(0xffffffffu, v, 8);
    v += __shfl_xor_sync(0xffffffffu, v, 4);
    v += __shfl_xor_sync(0xffffffffu, v, 2);
    v += __shfl_xor_sync(0xffffffffu, v, 1);
    return v;
}

// ASRC: 0 = A[row*lda + k]
//       1 = concat-pair view of s1 (k<250 -> focus row, else context row)
//       2 = tri-source (k<250 -> s1, k<500 -> eff, else x)
// ACT : 0 = relu, 1 = tanh, 2 = none
// Block: BM=32 rows x BN cols, 256 threads (8 warps x 32 lanes).
// Warp w owns rows [4w, 4w+4); lane owns BN/32 contiguous columns.
// LN row stats = warp shuffle reduction (warp covers the full row).
template <int BN, int ASRC, int ACT, bool DO_LN, bool DO_ATT>
__global__ __launch_bounds__(256)
void gemm_fused(const float* __restrict__ A, int lda, int Kdim, int N,
                const float* __restrict__ W,
                const float* __restrict__ bias,
                const float* __restrict__ gamma,
                const float* __restrict__ beta,
                const float* __restrict__ W2,
                const float* __restrict__ b2,
                const float* __restrict__ A2,
                const float* __restrict__ A3,
                float* __restrict__ C, int ldc)
{
    constexpr int BM = 32;
    constexpr int KT = 16;
    constexpr int TN = BN / 32;

    __shared__ float As[KT][BM + 4];   // +4 pad: 16B-aligned rows, low bank conflict
    __shared__ float Bs[KT][BN];
    __shared__ int   srcF[BM], srcC[BM];

    const int tid = threadIdx.x;
    const int tx  = tid & 31;
    const int ty  = tid >> 5;
    const int rowBase = blockIdx.x * BM;

    if (ASRC == 1) {
        if (tid < BM) {
            int r    = rowBase + tid;
            int bidx = r / (Kn * (Kn - 1));
            int rem  = r - bidx * (Kn * (Kn - 1));
            int i    = rem / (Kn - 1);
            int jj   = rem - i * (Kn - 1);
            int j    = jj + (jj >= i ? 1 : 0);   // idx[i] = [0..K-1] \ {i}, ascending
            srcF[tid] = bidx * Kn + i;
            srcC[tid] = bidx * Kn + j;
        }
        __syncthreads();
    }

    float acc[4][TN];
    #pragma unroll
    for (int i = 0; i < 4; ++i)
        #pragma unroll
        for (int j = 0; j < TN; ++j) acc[i][j] = 0.f;

    for (int kt = 0; kt < Kdim; kt += KT) {
        // --- stage A tile (k-major load for coalescing) ---
        #pragma unroll
        for (int it = 0; it < (BM * KT) / 256; ++it) {
            int idx = tid + it * 256;
            int kk  = idx & (KT - 1);
            int m   = idx / KT;
            int k   = kt + kk;
            float v = 0.f;
            if (k < Kdim) {
                if (ASRC == 0) {
                    v = A[(rowBase + m) * lda + k];
                } else if (ASRC == 1) {
                    v = (k < H1) ? A[srcF[m] * H1 + k]
                                 : A[srcC[m] * H1 + (k - H1)];
                } else {
                    int row = rowBase + m;
                    if (k < H1)            v = A [row * H1 + k];
                    else if (k < 2 * H1)   v = A2[row * H1 + (k - H1)];
                    else                   v = A3[row * Mx + (k - 2 * H1)];
                }
            }
            As[kk][m] = v;
        }
        // --- stage W tile ---
        #pragma unroll
        for (int it = 0; it < (KT * BN) / 256; ++it) {
            int idx = tid + it * 256;
            int n   = idx & (BN - 1);
            int kk  = idx / BN;
            int k   = kt + kk;
            Bs[kk][n] = (k < Kdim && n < N) ? W[k * N + n] : 0.f;
        }
        __syncthreads();

        // --- 4xTN register micro-tile ---
        #pragma unroll
        for (int kk = 0; kk < KT; ++kk) {
            float4 a4 = *(const float4*)(&As[kk][ty * 4]);
            float a[4] = {a4.x, a4.y, a4.z, a4.w};
            float bv[TN];
            #pragma unroll
            for (int j = 0; j < TN; j += 4) {
                float4 b4 = *(const float4*)(&Bs[kk][tx * TN + j]);
                bv[j] = b4.x; bv[j + 1] = b4.y; bv[j + 2] = b4.z; bv[j + 3] = b4.w;
            }
            #pragma unroll
            for (int i = 0; i < 4; ++i)
                #pragma unroll
                for (int j = 0; j < TN; ++j)
                    acc[i][j] = fmaf(a[i], bv[j], acc[i][j]);
        }
        __syncthreads();
    }

    // --- epilogue: bias + activation (+ LN over the row) (+ attention dot) ---
    const int cbase = tx * TN;
    float sum[4], ssq[4];
    #pragma unroll
    for (int i = 0; i < 4; ++i) { sum[i] = 0.f; ssq[i] = 0.f; }

    #pragma unroll
    for (int i = 0; i < 4; ++i) {
        #pragma unroll
        for (int j = 0; j < TN; ++j) {
            int c = cbase + j;
            float v = 0.f;
            if (c < N) {
                v = acc[i][j] + bias[c];
                if (ACT == 0)      v = fmaxf(v, 0.f);
                else if (ACT == 1) v = tanhf(v);
            }
            acc[i][j] = v;            // v==0 for padded cols -> stats exact
            sum[i] += v;
            ssq[i] += v * v;
        }
    }

    if constexpr (DO_LN) {
        const float invN = 1.f / (float)N;
        #pragma unroll
        for (int i = 0; i < 4; ++i) {
            float s   = warp_sum(sum[i]);
            float q   = warp_sum(ssq[i]);
            float mu  = s * invN;
            float var = q * invN - mu * mu;
            float inv = rsqrtf(var + EPS_LN);
            #pragma unroll
            for (int j = 0; j < TN; ++j) {
                int c = cbase + j;
                if (c < N)
                    acc[i][j] = (acc[i][j] - mu) * inv * gamma[c] + beta[c];
            }
        }
    }

    if constexpr (DO_ATT) {
        // att = sigmoid(LN(h) @ W2 + b2); only the scalar is stored.
        #pragma unroll
        for (int i = 0; i < 4; ++i) {
            float d = 0.f;
            #pragma unroll
            for (int j = 0; j < TN; ++j) {
                int c = cbase + j;
                if (c < N) d += acc[i][j] * W2[c];
            }
            d = warp_sum(d);
            if (tx == 0) {
                int row = rowBase + ty * 4 + i;
                float z = d + b2[0];
                C[row] = 1.f / (1.f + expf(-z));
            }
        }
    } else {
        #pragma unroll
        for (int i = 0; i < 4; ++i) {
            int row = rowBase + ty * 4 + i;
            #pragma unroll
            for (int j = 0; j < TN; ++j) {
                int c = cbase + j;
                if (c < N) C[row * ldc + c] = acc[i][j];
            }
        }
    }
}

// eff[bk, c] = sum_{j<7} ctx[bk*7+j, c] * att[bk*7+j]
__global__ __launch_bounds__(256)
void effect_kernel(const float* __restrict__ ctx,
                   const float* __restrict__ att,
                   float* __restrict__ eff)
{
    const int bk = blockIdx.x;
    __shared__ float a[Kn - 1];
    if (threadIdx.x < Kn - 1) a[threadIdx.x] = att[bk * (Kn - 1) + threadIdx.x];
    __syncthreads();
    int c = threadIdx.x;
    if (c < H1) {
        const float* base = ctx + bk * (Kn - 1) * H1;
        float s = 0.f;
        #pragma unroll
        for (int j = 0; j < Kn - 1; ++j)
            s = fmaf(base[j * H1 + c], a[j], s);
        eff[bk * H1 + c] = s;
    }
}

extern "C" void kernel_launch(void* const* d_in, const int* in_sizes, int n_in,
                              void* d_out, int out_size)
{
    const float* x      = (const float*)d_in[0];
    const float* state  = (const float*)d_in[1];
    const float* enc_W  = (const float*)d_in[2];
    const float* enc_b  = (const float*)d_in[3];
    const float* enc_g  = (const float*)d_in[4];
    const float* enc_bt = (const float*)d_in[5];
    const float* core_W = (const float*)d_in[6];
    const float* core_b = (const float*)d_in[7];
    const float* core_g = (const float*)d_in[8];
    const float* core_bt= (const float*)d_in[9];
    const float* ctx_W  = (const float*)d_in[10];
    const float* ctx_b  = (const float*)d_in[11];
    const float* ctx_g  = (const float*)d_in[12];
    const float* ctx_bt = (const float*)d_in[13];
    const float* att_W1 = (const float*)d_in[14];
    const float* att_b1 = (const float*)d_in[15];
    const float* att_g  = (const float*)d_in[16];
    const float* att_bt = (const float*)d_in[17];
    const float* att_W2 = (const float*)d_in[18];
    const float* att_b2 = (const float*)d_in[19];
    const float* out_W  = (const float*)d_in[20];
    const float* out_b  = (const float*)d_in[21];
    float* out = (float*)d_out;

    float *p_s1, *p_core, *p_ctx, *p_att, *p_eff;
    cudaGetSymbolAddress((void**)&p_s1,   g_s1);
    cudaGetSymbolAddress((void**)&p_core, g_core);
    cudaGetSymbolAddress((void**)&p_ctx,  g_ctx);
    cudaGetSymbolAddress((void**)&p_att,  g_att);
    cudaGetSymbolAddress((void**)&p_eff,  g_eff);

    // s1 = LN(relu(state @ enc_W + b))
    gemm_fused<256, 0, 0, true, false><<<BK / 32, 256>>>(
        state, H1, H1, H1, enc_W, enc_b, enc_g, enc_bt,
        nullptr, nullptr, nullptr, nullptr, p_s1, H1);

    // core = LN(relu(concat(fs,cs) @ core_W + b)) — pair matrix built on the fly
    gemm_fused<256, 1, 0, true, false><<<RR / 32, 256>>>(
        p_s1, H1, 2 * H1, H1, core_W, core_b, core_g, core_bt,
        nullptr, nullptr, nullptr, nullptr, p_core, H1);

    // ctx = LN(relu(core @ ctx_W + b))
    gemm_fused<256, 0, 0, true, false><<<RR / 32, 256>>>(
        p_core, H1, H1, H1, ctx_W, ctx_b, ctx_g, ctx_bt,
        nullptr, nullptr, nullptr, nullptr, p_ctx, H1);

    // att = sigmoid(LN(tanh(core @ att_W1 + b1)) @ att_W2 + b2)  (BN=128, N=100)
    gemm_fused<128, 0, 1, true, true><<<RR / 32, 256>>>(
        p_core, H1, H1, HAn, att_W1, att_b1, att_g, att_bt,
        att_W2, att_b2, nullptr, nullptr, p_att, 0);

    // eff = 7-way attention-weighted reduction of ctx
    effect_kernel<<<BK, 256>>>(p_ctx, p_att, p_eff);

    // out = concat(s1, eff, x) @ out_W + out_b  — tri-source A, no concat buffer
    gemm_fused<256, 2, 2, false, false><<<BK / 32, 256>>>(
        p_s1, H1, 2 * H1 + Mx, H1, out_W, out_b,
        nullptr, nullptr, nullptr, nullptr, p_eff, x, out, H1);
}

// round 4
// speedup vs baseline: 1.4011x; 1.4011x over previous
#include <cuda_runtime.h>
#include <math.h>

// ---------------------------------------------------------------------------
// R-NEM cell, fused GEMM(+bias+act+LayerNorm[+attention]) kernels, fp32 SIMT.
// R3: 8x8 register micro-tile (BM=64) to cut LDS bytes/FMA from 1.5 -> 1.0;
//     R2 profile showed L1 (smem crossbar) at 83% with fma at only 45%.
// ---------------------------------------------------------------------------

#define EPS_LN 1e-5f

static constexpr int Bn  = 2048;
static constexpr int Kn  = 8;
static constexpr int BK  = Bn * Kn;          // 16384 entity rows
static constexpr int RR  = BK * (Kn - 1);    // 114688 pair rows
static constexpr int H1  = 250;
static constexpr int Mx  = 576;
static constexpr int HAn = 100;

// Scratch (device globals: allocation-free per harness rules)
__device__ float g_s1  [BK * H1];
__device__ float g_core[RR * H1];
__device__ float g_ctx [RR * H1];
__device__ float g_att [RR];
__device__ float g_eff [BK * H1];

__device__ __forceinline__ float warp_sum(float v) {
    v += __shfl_xor_sync(0xffffffffu, v, 16);
    v += __shfl_xor_sync(0xffffffffu, v, 8);
    v += __shfl_xor_sync(0xffffffffu, v, 4);
    v += __shfl_xor_sync(0xffffffffu, v, 2);
    v += __shfl_xor_sync(0xffffffffu, v, 1);
    return v;
}

// ASRC: 0 = A[row*lda + k]
//       1 = concat-pair view of s1 (k<250 -> focus row, else context row)
//       2 = tri-source (k<250 -> s1, k<500 -> eff, else x)
// ACT : 0 = relu, 1 = tanh, 2 = none
// Block: BM=64 rows x BN cols, 256 threads (8 warps).
// Warp w owns rows [8w, 8w+8); lane owns TN=BN/32 contiguous columns.
// Each warp covers a full output row -> LN stats via shuffle reduction.
template <int BN, int ASRC, int ACT, bool DO_LN, bool DO_ATT>
__global__ __launch_bounds__(256, 2)
void gemm_fused(const float* __restrict__ A, int lda, int Kdim, int N,
                const float* __restrict__ W,
                const float* __restrict__ bias,
                const float* __restrict__ gamma,
                const float* __restrict__ beta,
                const float* __restrict__ W2,
                const float* __restrict__ b2,
                const float* __restrict__ A2,
                const float* __restrict__ A3,
                float* __restrict__ C, int ldc)
{
    constexpr int BM = 64;
    constexpr int KT = 16;
    constexpr int TN = BN / 32;
    constexpr int RM = 8;              // rows per thread (= rows per warp)

    // +4 pad: staging STS (column writes, stride BM+4) is only 2-way conflicted
    // while rows stay 16B-aligned for the broadcast float4 reads in the mainloop.
    __shared__ float As[KT][BM + 4];
    __shared__ float Bs[KT][BN];
    __shared__ int   srcF[BM], srcC[BM];

    const int tid = threadIdx.x;
    const int tx  = tid & 31;
    const int ty  = tid >> 5;
    const int rowBase = blockIdx.x * BM;

    if (ASRC == 1) {
        if (tid < BM) {
            int r    = rowBase + tid;
            int bidx = r / (Kn * (Kn - 1));
            int rem  = r - bidx * (Kn * (Kn - 1));
            int i    = rem / (Kn - 1);
            int jj   = rem - i * (Kn - 1);
            int j    = jj + (jj >= i ? 1 : 0);   // idx[i] = [0..K-1] \ {i}
            srcF[tid] = bidx * Kn + i;
            srcC[tid] = bidx * Kn + j;
        }
        __syncthreads();
    }

    float acc[RM][TN];
    #pragma unroll
    for (int i = 0; i < RM; ++i)
        #pragma unroll
        for (int j = 0; j < TN; ++j) acc[i][j] = 0.f;

    for (int kt = 0; kt < Kdim; kt += KT) {
        // --- stage A tile, k-major so LDG stays coalesced (64B segments) ---
        #pragma unroll
        for (int it = 0; it < (BM * KT) / 256; ++it) {
            int idx = tid + it * 256;
            int kk  = idx & (KT - 1);
            int m   = idx >> 4;           // KT = 16
            int k   = kt + kk;
            float v = 0.f;
            if (k < Kdim) {
                if (ASRC == 0) {
                    v = A[(rowBase + m) * lda + k];
                } else if (ASRC == 1) {
                    v = (k < H1) ? A[srcF[m] * H1 + k]
                                 : A[srcC[m] * H1 + (k - H1)];
                } else {
                    int row = rowBase + m;
                    if (k < H1)            v = A [row * H1 + k];
                    else if (k < 2 * H1)   v = A2[row * H1 + (k - H1)];
                    else                   v = A3[row * Mx + (k - 2 * H1)];
                }
            }
            As[kk][m] = v;
        }
        // --- stage W tile (n-major: coalesced LDG, conflict-free STS) ---
        #pragma unroll
        for (int it = 0; it < (KT * BN) / 256; ++it) {
            int idx = tid + it * 256;
            int n   = idx & (BN - 1);
            int kk  = idx / BN;
            int k   = kt + kk;
            Bs[kk][n] = (k < Kdim && n < N) ? W[k * N + n] : 0.f;
        }
        __syncthreads();

        // --- 8xTN register micro-tile: 4 LDS.128 feed RM*TN FMAs ---
        #pragma unroll
        for (int kk = 0; kk < KT; ++kk) {
            float a[RM];
            float4 a0 = *(const float4*)(&As[kk][ty * RM]);      // broadcast
            float4 a1 = *(const float4*)(&As[kk][ty * RM + 4]);  // broadcast
            a[0] = a0.x; a[1] = a0.y; a[2] = a0.z; a[3] = a0.w;
            a[4] = a1.x; a[5] = a1.y; a[6] = a1.z; a[7] = a1.w;
            float bv[TN];
            #pragma unroll
            for (int j = 0; j < TN; j += 4) {
                float4 b4 = *(const float4*)(&Bs[kk][tx * TN + j]);
                bv[j] = b4.x; bv[j + 1] = b4.y; bv[j + 2] = b4.z; bv[j + 3] = b4.w;
            }
            #pragma unroll
            for (int i = 0; i < RM; ++i)
                #pragma unroll
                for (int j = 0; j < TN; ++j)
                    acc[i][j] = fmaf(a[i], bv[j], acc[i][j]);
        }
        __syncthreads();
    }

    // --- epilogue: bias + activation (+ LN) (+ attention scalar) ---
    const int cbase = tx * TN;

    #pragma unroll
    for (int i = 0; i < RM; ++i) {
        float sum = 0.f, ssq = 0.f;
        #pragma unroll
        for (int j = 0; j < TN; ++j) {
            int c = cbase + j;
            float v = 0.f;
            if (c < N) {
                v = acc[i][j] + bias[c];
                if (ACT == 0)      v = fmaxf(v, 0.f);
                else if (ACT == 1) v = tanhf(v);
            }
            acc[i][j] = v;               // v==0 for padded cols -> exact stats
            sum += v;
            ssq += v * v;
        }

        if constexpr (DO_LN) {
            const float invN = 1.f / (float)N;
            float s   = warp_sum(sum);
            float q   = warp_sum(ssq);
            float mu  = s * invN;
            float var = q * invN - mu * mu;
            float inv = rsqrtf(var + EPS_LN);
            #pragma unroll
            for (int j = 0; j < TN; ++j) {
                int c = cbase + j;
                if (c < N)
                    acc[i][j] = (acc[i][j] - mu) * inv * gamma[c] + beta[c];
            }
        }

        if constexpr (DO_ATT) {
            float d = 0.f;
            #pragma unroll
            for (int j = 0; j < TN; ++j) {
                int c = cbase + j;
                if (c < N) d += acc[i][j] * W2[c];
            }
            d = warp_sum(d);
            if (tx == 0) {
                int row = rowBase + ty * RM + i;
                float z = d + b2[0];
                C[row] = 1.f / (1.f + expf(-z));
            }
        } else {
            int row = rowBase + ty * RM + i;
            #pragma unroll
            for (int j = 0; j < TN; ++j) {
                int c = cbase + j;
                if (c < N) C[row * ldc + c] = acc[i][j];
            }
        }
    }
}

// eff[bk, c] = sum_{j<7} ctx[bk*7+j, c] * att[bk*7+j]
__global__ __launch_bounds__(256)
void effect_kernel(const float* __restrict__ ctx,
                   const float* __restrict__ att,
                   float* __restrict__ eff)
{
    const int bk = blockIdx.x;
    __shared__ float a[Kn - 1];
    if (threadIdx.x < Kn - 1) a[threadIdx.x] = att[bk * (Kn - 1) + threadIdx.x];
    __syncthreads();
    int c = threadIdx.x;
    if (c < H1) {
        const float* base = ctx + bk * (Kn - 1) * H1;
        float s = 0.f;
        #pragma unroll
        for (int j = 0; j < Kn - 1; ++j)
            s = fmaf(base[j * H1 + c], a[j], s);
        eff[bk * H1 + c] = s;
    }
}

extern "C" void kernel_launch(void* const* d_in, const int* in_sizes, int n_in,
                              void* d_out, int out_size)
{
    const float* x      = (const float*)d_in[0];
    const float* state  = (const float*)d_in[1];
    const float* enc_W  = (const float*)d_in[2];
    const float* enc_b  = (const float*)d_in[3];
    const float* enc_g  = (const float*)d_in[4];
    const float* enc_bt = (const float*)d_in[5];
    const float* core_W = (const float*)d_in[6];
    const float* core_b = (const float*)d_in[7];
    const float* core_g = (const float*)d_in[8];
    const float* core_bt= (const float*)d_in[9];
    const float* ctx_W  = (const float*)d_in[10];
    const float* ctx_b  = (const float*)d_in[11];
    const float* ctx_g  = (const float*)d_in[12];
    const float* ctx_bt = (const float*)d_in[13];
    const float* att_W1 = (const float*)d_in[14];
    const float* att_b1 = (const float*)d_in[15];
    const float* att_g  = (const float*)d_in[16];
    const float* att_bt = (const float*)d_in[17];
    const float* att_W2 = (const float*)d_in[18];
    const float* att_b2 = (const float*)d_in[19];
    const float* out_W  = (const float*)d_in[20];
    const float* out_b  = (const float*)d_in[21];
    float* out = (float*)d_out;

    float *p_s1, *p_core, *p_ctx, *p_att, *p_eff;
    cudaGetSymbolAddress((void**)&p_s1,   g_s1);
    cudaGetSymbolAddress((void**)&p_core, g_core);
    cudaGetSymbolAddress((void**)&p_ctx,  g_ctx);
    cudaGetSymbolAddress((void**)&p_att,  g_att);
    cudaGetSymbolAddress((void**)&p_eff,  g_eff);

    // s1 = LN(relu(state @ enc_W + b))
    gemm_fused<256, 0, 0, true, false><<<BK / 64, 256>>>(
        state, H1, H1, H1, enc_W, enc_b, enc_g, enc_bt,
        nullptr, nullptr, nullptr, nullptr, p_s1, H1);

    // core = LN(relu(concat(fs,cs) @ core_W + b)) — pair matrix built on the fly
    gemm_fused<256, 1, 0, true, false><<<RR / 64, 256>>>(
        p_s1, H1, 2 * H1, H1, core_W, core_b, core_g, core_bt,
        nullptr, nullptr, nullptr, nullptr, p_core, H1);

    // ctx = LN(relu(core @ ctx_W + b))
    gemm_fused<256, 0, 0, true, false><<<RR / 64, 256>>>(
        p_core, H1, H1, H1, ctx_W, ctx_b, ctx_g, ctx_bt,
        nullptr, nullptr, nullptr, nullptr, p_ctx, H1);

    // att = sigmoid(LN(tanh(core @ att_W1 + b1)) @ att_W2 + b2)  (BN=128, N=100)
    gemm_fused<128, 0, 1, true, true><<<RR / 64, 256>>>(
        p_core, H1, H1, HAn, att_W1, att_b1, att_g, att_bt,
        att_W2, att_b2, nullptr, nullptr, p_att, 0);

    // eff = 7-way attention-weighted reduction of ctx
    effect_kernel<<<BK, 256>>>(p_ctx, p_att, p_eff);

    // out = concat(s1, eff, x) @ out_W + out_b  — tri-source A, no concat buffer
    gemm_fused<256, 2, 2, false, false><<<BK / 64, 256>>>(
        p_s1, H1, 2 * H1 + Mx, H1, out_W, out_b,
        nullptr, nullptr, nullptr, nullptr, p_eff, x, out, H1);
}

// round 6
// speedup vs baseline: 1.8581x; 1.3262x over previous
#include <cuda_runtime.h>
#include <cuda_bf16.h>
#include <mma.h>
#include <math.h>
#include <stdint.h>

using namespace nvcuda;

// ---------------------------------------------------------------------------
// R-NEM cell on tensor cores via portable wmma (HMMA mma.sync, bf16).
// fp32 emulated as bf16 hi/lo 3-term: D = AhBh + AhBl + AlBh, fp32 accum.
// (tcgen05 is unavailable: harness PTX target is compute_103, no 'a' suffix.)
// Fused epilogue: bias + relu/tanh + LayerNorm (+ attention scalar).
// ---------------------------------------------------------------------------

#define EPS_LN 1e-5f

static constexpr int Bn  = 2048;
static constexpr int Kn  = 8;
static constexpr int BK  = Bn * Kn;          // 16384 entity rows
static constexpr int RR  = BK * (Kn - 1);    // 114688 pair rows
static constexpr int H1  = 250;
static constexpr int Mx  = 576;

// fp32 scratch
__device__ float g_s1  [BK * H1];
__device__ float g_core[RR * H1];
__device__ float g_ctx [RR * H1];
__device__ float g_att [RR];
__device__ float g_eff [BK * H1];

// Pre-split weights, layout [Kpad][NT] row-major (k-major, n contiguous)
__device__ __nv_bfloat16 g_enc_h [256 * 256],  g_enc_l [256 * 256];
__device__ __nv_bfloat16 g_core_h[512 * 256],  g_core_l[512 * 256];
__device__ __nv_bfloat16 g_ctx_h [256 * 256],  g_ctx_l [256 * 256];
__device__ __nv_bfloat16 g_att_h [256 * 128],  g_att_l [256 * 128];
__device__ __nv_bfloat16 g_out_h [1088 * 256], g_out_l [1088 * 256];

// ---------------- weight prep: W[K,N] fp32 -> [Kpad][NT] bf16 hi/lo --------
__global__ __launch_bounds__(256)
void prep_w(const float* __restrict__ W, int K, int N, int Kpad, int NT,
            __nv_bfloat16* __restrict__ bh, __nv_bfloat16* __restrict__ bl)
{
    int idx = blockIdx.x * 256 + threadIdx.x;
    if (idx >= Kpad * NT) return;
    int k = idx / NT;
    int n = idx - k * NT;
    float v = (k < K && n < N) ? W[k * N + n] : 0.f;
    __nv_bfloat16 h = __float2bfloat16(v);
    float lo = v - __bfloat162float(h);
    bh[idx] = h;
    bl[idx] = __float2bfloat16(lo);
}

// ---------------- fused wmma GEMM ------------------------------------------
// NT: padded N tile (256 or 128; block covers full row). N: logical cols.
// KDIM: logical K.  ASRC: 0 direct, 1 pair-concat of s1, 2 tri-concat.
// ACT: 0 relu, 1 tanh, 2 none.
template <int NT, int N, int KDIM, int ASRC, int ACT, bool DO_LN, bool DO_ATT>
__global__ __launch_bounds__(256, 1)
void tc_gemm(const float* __restrict__ A,
             const float* __restrict__ A2,
             const float* __restrict__ A3,
             const __nv_bfloat16* __restrict__ Bh,
             const __nv_bfloat16* __restrict__ Bl,
             const float* __restrict__ bias,
             const float* __restrict__ gamma,
             const float* __restrict__ beta,
             const float* __restrict__ W2,
             const float* __restrict__ b2,
             float* __restrict__ C, int ldc)
{
    constexpr int KC   = (KDIM + 63) / 64;       // 64-wide k chunks
    constexpr int LDA  = 80;                     // 160B row stride (32B mult)
    constexpr int LDB  = NT + 16;                // 32B-mult row stride
    constexpr int CLD  = NT + 8;                 // f32 epilogue stride (32B mult)
    constexpr int WN   = NT / 64;                // warps along n
    constexpr int WM   = 8 / WN;                 // warps along m
    constexpr int MROW = 128 / WM;               // rows per warp
    constexpr int MF   = MROW / 16;              // m frags per warp
    constexpr int NF   = 4;                      // n frags per warp (64 cols)

    constexpr int OFF_AH = 0;
    constexpr int OFF_AL = OFF_AH + 128 * LDA;           // bf16 elements
    constexpr int OFF_BH = OFF_AL + 128 * LDA;
    constexpr int OFF_BL = OFF_BH + 64 * LDB;

    extern __shared__ char smem[];
    __nv_bfloat16* Ash = (__nv_bfloat16*)smem + OFF_AH;
    __nv_bfloat16* Asl = (__nv_bfloat16*)smem + OFF_AL;
    __nv_bfloat16* Bsh = (__nv_bfloat16*)smem + OFF_BH;
    __nv_bfloat16* Bsl = (__nv_bfloat16*)smem + OFF_BL;
    float*         Cs  = (float*)smem;                    // reused post-mainloop

    const int tid  = threadIdx.x;
    const int wid  = tid >> 5;
    const int rowBase = blockIdx.x * 128;

    // A gather source: thread loads row tid/2, k-half tid&1 (32 k's)
    const int arow  = tid >> 1;
    const int ahalf = tid & 1;
    const int r     = rowBase + arow;
    const float* pF = nullptr;
    const float* pC = nullptr;
    if (ASRC == 0) {
        pF = A + (size_t)r * KDIM;
    } else if (ASRC == 1) {
        int bidx = r / (Kn * (Kn - 1));
        int rem  = r - bidx * (Kn * (Kn - 1));
        int i    = rem / (Kn - 1);
        int jj   = rem - i * (Kn - 1);
        int j    = jj + (jj >= i ? 1 : 0);   // idx[i] = [0..K-1] \ {i}
        pF = A + (size_t)(bidx * Kn + i) * H1;
        pC = A + (size_t)(bidx * Kn + j) * H1;
    }

    const int wm = wid / WN;
    const int wn = wid % WN;
    const int mrow0 = wm * MROW;
    const int ncol0 = wn * 64;

    wmma::fragment<wmma::accumulator, 16, 16, 16, float> acc[MF][NF];
    #pragma unroll
    for (int i = 0; i < MF; ++i)
        #pragma unroll
        for (int j = 0; j < NF; ++j)
            wmma::fill_fragment(acc[i][j], 0.f);

    for (int c = 0; c < KC; ++c) {
        const int kc = c * 64;

        // --- stage A: gather fp32, hi/lo split, packed bf16x2 stores ---
        {
            const int kb = kc + ahalf * 32;
            __nv_bfloat16* dh = Ash + arow * LDA + ahalf * 32;
            __nv_bfloat16* dl = Asl + arow * LDA + ahalf * 32;
            #pragma unroll
            for (int j = 0; j < 32; j += 2) {
                float v0 = 0.f, v1 = 0.f;
                int k0 = kb + j, k1 = kb + j + 1;
                if (ASRC == 0) {
                    if (k0 < KDIM) v0 = pF[k0];
                    if (k1 < KDIM) v1 = pF[k1];
                } else if (ASRC == 1) {
                    v0 = (k0 < H1) ? pF[k0] : ((k0 < 2 * H1) ? pC[k0 - H1] : 0.f);
                    v1 = (k1 < H1) ? pF[k1] : ((k1 < 2 * H1) ? pC[k1 - H1] : 0.f);
                } else {
                    if (k0 < H1)          v0 = A [(size_t)r * H1 + k0];
                    else if (k0 < 2 * H1) v0 = A2[(size_t)r * H1 + (k0 - H1)];
                    else if (k0 < KDIM)   v0 = A3[(size_t)r * Mx + (k0 - 2 * H1)];
                    if (k1 < H1)          v1 = A [(size_t)r * H1 + k1];
                    else if (k1 < 2 * H1) v1 = A2[(size_t)r * H1 + (k1 - H1)];
                    else if (k1 < KDIM)   v1 = A3[(size_t)r * Mx + (k1 - 2 * H1)];
                }
                __nv_bfloat16 h0 = __float2bfloat16(v0);
                __nv_bfloat16 h1 = __float2bfloat16(v1);
                __nv_bfloat16 l0 = __float2bfloat16(v0 - __bfloat162float(h0));
                __nv_bfloat16 l1 = __float2bfloat16(v1 - __bfloat162float(h1));
                *(__nv_bfloat162*)(dh + j) = __nv_bfloat162(h0, h1);
                *(__nv_bfloat162*)(dl + j) = __nv_bfloat162(l0, l1);
            }
        }
        // --- stage B: pre-split bf16 [Kpad][NT], 16B vector copies ---
        {
            constexpr int UPR = NT / 8;          // 16B units per k-row
            constexpr int TOT = 64 * UPR;        // units per matrix
            #pragma unroll
            for (int t = 0; t < TOT / 256; ++t) {
                int u  = tid + t * 256;
                int k  = u / UPR;
                int c8 = u - k * UPR;
                size_t go = (size_t)(kc + k) * NT + c8 * 8;
                uint4 vh = *(const uint4*)(Bh + go);
                uint4 vl = *(const uint4*)(Bl + go);
                int so = k * LDB + c8 * 8;
                *(uint4*)(Bsh + so) = vh;
                *(uint4*)(Bsl + so) = vl;
            }
        }
        __syncthreads();

        // --- wmma: 4 k16 steps, MFxNF tiles, 3 terms ---
        #pragma unroll
        for (int s = 0; s < 4; ++s) {
            wmma::fragment<wmma::matrix_a, 16, 16, 16, __nv_bfloat16, wmma::row_major> ah[MF], al[MF];
            #pragma unroll
            for (int i = 0; i < MF; ++i) {
                const __nv_bfloat16* pa = Ash + (mrow0 + i * 16) * LDA + s * 16;
                const __nv_bfloat16* pl = Asl + (mrow0 + i * 16) * LDA + s * 16;
                wmma::load_matrix_sync(ah[i], pa, LDA);
                wmma::load_matrix_sync(al[i], pl, LDA);
            }
            #pragma unroll
            for (int j = 0; j < NF; ++j) {
                wmma::fragment<wmma::matrix_b, 16, 16, 16, __nv_bfloat16, wmma::row_major> bh, bl;
                const __nv_bfloat16* pb = Bsh + (s * 16) * LDB + ncol0 + j * 16;
                const __nv_bfloat16* ql = Bsl + (s * 16) * LDB + ncol0 + j * 16;
                wmma::load_matrix_sync(bh, pb, LDB);
                wmma::load_matrix_sync(bl, ql, LDB);
                #pragma unroll
                for (int i = 0; i < MF; ++i) {
                    wmma::mma_sync(acc[i][j], ah[i], bh, acc[i][j]);
                    wmma::mma_sync(acc[i][j], ah[i], bl, acc[i][j]);
                    wmma::mma_sync(acc[i][j], al[i], bh, acc[i][j]);
                }
            }
        }
        __syncthreads();
    }

    // --- dump accumulators to SMEM fp32 (reuses staging region) ---
    #pragma unroll
    for (int i = 0; i < MF; ++i)
        #pragma unroll
        for (int j = 0; j < NF; ++j)
            wmma::store_matrix_sync(Cs + (mrow0 + i * 16) * CLD + ncol0 + j * 16,
                                    acc[i][j], CLD, wmma::mem_row_major);
    __syncthreads();

    // --- epilogue: 2 threads per row; shfl_xor(1) combines the halves ---
    constexpr int HC = NT / 2;
    const int row  = tid >> 1;
    const int half = tid & 1;
    const float* crow = Cs + row * CLD + half * HC;

    float sum = 0.f, ssq = 0.f;
    #pragma unroll 4
    for (int j = 0; j < HC; ++j) {
        int cc = half * HC + j;
        float v = 0.f;
        if (cc < N) {
            v = crow[j] + bias[cc];
            if (ACT == 0)      v = fmaxf(v, 0.f);
            else if (ACT == 1) v = tanhf(v);
        }
        sum += v; ssq += v * v;
    }

    float mu = 0.f, inv = 1.f;
    if constexpr (DO_LN) {
        float s = sum + __shfl_xor_sync(0xffffffffu, sum, 1);
        float q = ssq + __shfl_xor_sync(0xffffffffu, ssq, 1);
        mu = s / (float)N;
        float var = q / (float)N - mu * mu;
        inv = rsqrtf(var + EPS_LN);
    }

    if constexpr (DO_ATT) {
        float d = 0.f;
        #pragma unroll 4
        for (int j = 0; j < HC; ++j) {
            int cc = half * HC + j;
            if (cc < N) {
                float v = crow[j] + bias[cc];
                v = tanhf(v);
                v = (v - mu) * inv * gamma[cc] + beta[cc];
                d += v * W2[cc];
            }
        }
        d += __shfl_xor_sync(0xffffffffu, d, 1);
        if (half == 0) {
            float z = d + b2[0];
            C[rowBase + row] = 1.f / (1.f + expf(-z));
        }
    } else {
        float* orow = C + (size_t)(rowBase + row) * ldc + half * HC;
        #pragma unroll 4
        for (int j = 0; j < HC; ++j) {
            int cc = half * HC + j;
            if (cc < N) {
                float v = crow[j] + bias[cc];
                if (ACT == 0)      v = fmaxf(v, 0.f);
                else if (ACT == 1) v = tanhf(v);
                if (DO_LN)
                    v = (v - mu) * inv * gamma[cc] + beta[cc];
                orow[j] = v;
            }
        }
    }
}

// eff[bk, c] = sum_{j<7} ctx[bk*7+j, c] * att[bk*7+j]
__global__ __launch_bounds__(256)
void effect_kernel(const float* __restrict__ ctx,
                   const float* __restrict__ att,
                   float* __restrict__ eff)
{
    const int bk = blockIdx.x;
    __shared__ float a[Kn - 1];
    if (threadIdx.x < Kn - 1) a[threadIdx.x] = att[bk * (Kn - 1) + threadIdx.x];
    __syncthreads();
    int c = threadIdx.x;
    if (c < H1) {
        const float* base = ctx + (size_t)bk * (Kn - 1) * H1;
        float s = 0.f;
        #pragma unroll
        for (int j = 0; j < Kn - 1; ++j)
            s = fmaf(base[j * H1 + c], a[j], s);
        eff[bk * H1 + c] = s;
    }
}

extern "C" void kernel_launch(void* const* d_in, const int* in_sizes, int n_in,
                              void* d_out, int out_size)
{
    const float* x      = (const float*)d_in[0];
    const float* state  = (const float*)d_in[1];
    const float* enc_W  = (const float*)d_in[2];
    const float* enc_b  = (const float*)d_in[3];
    const float* enc_g  = (const float*)d_in[4];
    const float* enc_bt = (const float*)d_in[5];
    const float* core_W = (const float*)d_in[6];
    const float* core_b = (const float*)d_in[7];
    const float* core_g = (const float*)d_in[8];
    const float* core_bt= (const float*)d_in[9];
    const float* ctx_W  = (const float*)d_in[10];
    const float* ctx_b  = (const float*)d_in[11];
    const float* ctx_g  = (const float*)d_in[12];
    const float* ctx_bt = (const float*)d_in[13];
    const float* att_W1 = (const float*)d_in[14];
    const float* att_b1 = (const float*)d_in[15];
    const float* att_g  = (const float*)d_in[16];
    const float* att_bt = (const float*)d_in[17];
    const float* att_W2 = (const float*)d_in[18];
    const float* att_b2 = (const float*)d_in[19];
    const float* out_W  = (const float*)d_in[20];
    const float* out_b  = (const float*)d_in[21];
    float* out = (float*)d_out;

    float *p_s1, *p_core, *p_ctx, *p_att, *p_eff;
    cudaGetSymbolAddress((void**)&p_s1,   g_s1);
    cudaGetSymbolAddress((void**)&p_core, g_core);
    cudaGetSymbolAddress((void**)&p_ctx,  g_ctx);
    cudaGetSymbolAddress((void**)&p_att,  g_att);
    cudaGetSymbolAddress((void**)&p_eff,  g_eff);

    __nv_bfloat16 *ench, *encl, *corh, *corl, *ctxh, *ctxl, *atth, *attl, *outh, *outl;
    cudaGetSymbolAddress((void**)&ench, g_enc_h);  cudaGetSymbolAddress((void**)&encl, g_enc_l);
    cudaGetSymbolAddress((void**)&corh, g_core_h); cudaGetSymbolAddress((void**)&corl, g_core_l);
    cudaGetSymbolAddress((void**)&ctxh, g_ctx_h);  cudaGetSymbolAddress((void**)&ctxl, g_ctx_l);
    cudaGetSymbolAddress((void**)&atth, g_att_h);  cudaGetSymbolAddress((void**)&attl, g_att_l);
    cudaGetSymbolAddress((void**)&outh, g_out_h);  cudaGetSymbolAddress((void**)&outl, g_out_l);

    // SMEM: stage = 2*128*80*2 + 2*64*(NT+16)*2 ; epilogue = 128*(NT+8)*4
    constexpr int SM256 = 128 * (256 + 8) * 4;   // 135168 (> stage 110592)
    constexpr int SM128 = 2 * 128 * 80 * 2 + 2 * 64 * 144 * 2;  // 77824 (> cs 69632)
    cudaFuncSetAttribute(tc_gemm<256, 250, 250, 0, 0, true, false>,
                         cudaFuncAttributeMaxDynamicSharedMemorySize, SM256);
    cudaFuncSetAttribute(tc_gemm<256, 250, 500, 1, 0, true, false>,
                         cudaFuncAttributeMaxDynamicSharedMemorySize, SM256);
    cudaFuncSetAttribute(tc_gemm<128, 100, 250, 0, 1, true, true>,
                         cudaFuncAttributeMaxDynamicSharedMemorySize, SM128);
    cudaFuncSetAttribute(tc_gemm<256, 250, 1076, 2, 2, false, false>,
                         cudaFuncAttributeMaxDynamicSharedMemorySize, SM256);

    // --- weight prep (hi/lo split, [Kpad][NT]) ---
    prep_w<<<(256  * 256 + 255) / 256, 256>>>(enc_W,  250,  250, 256,  256, ench, encl);
    prep_w<<<(512  * 256 + 255) / 256, 256>>>(core_W, 500,  250, 512,  256, corh, corl);
    prep_w<<<(256  * 256 + 255) / 256, 256>>>(ctx_W,  250,  250, 256,  256, ctxh, ctxl);
    prep_w<<<(256  * 128 + 255) / 256, 256>>>(att_W1, 250,  100, 256,  128, atth, attl);
    prep_w<<<(1088 * 256 + 255) / 256, 256>>>(out_W,  1076, 250, 1088, 256, outh, outl);

    // s1 = LN(relu(state @ enc_W + b))
    tc_gemm<256, 250, 250, 0, 0, true, false><<<BK / 128, 256, SM256>>>(
        state, nullptr, nullptr, ench, encl,
        enc_b, enc_g, enc_bt, nullptr, nullptr, p_s1, H1);

    // core = LN(relu(concat(fs,cs) @ core_W + b)) — pair gather in A loader
    tc_gemm<256, 250, 500, 1, 0, true, false><<<RR / 128, 256, SM256>>>(
        p_s1, nullptr, nullptr, corh, corl,
        core_b, core_g, core_bt, nullptr, nullptr, p_core, H1);

    // ctx = LN(relu(core @ ctx_W + b))
    tc_gemm<256, 250, 250, 0, 0, true, false><<<RR / 128, 256, SM256>>>(
        p_core, nullptr, nullptr, ctxh, ctxl,
        ctx_b, ctx_g, ctx_bt, nullptr, nullptr, p_ctx, H1);

    // att = sigmoid(LN(tanh(core @ att_W1 + b1)) @ att_W2 + b2)
    tc_gemm<128, 100, 250, 0, 1, true, true><<<RR / 128, 256, SM128>>>(
        p_core, nullptr, nullptr, atth, attl,
        att_b1, att_g, att_bt, att_W2, att_b2, p_att, 0);

    // eff = 7-way attention-weighted reduction of ctx
    effect_kernel<<<BK, 256>>>(p_ctx, p_att, p_eff);

    // out = concat(s1, eff, x) @ out_W + out_b — tri-source A loader
    tc_gemm<256, 250, 1076, 2, 2, false, false><<<BK / 128, 256, SM256>>>(
        p_s1, p_eff, x, outh, outl,
        out_b, nullptr, nullptr, nullptr, nullptr, out, H1);
}

// round 7
// speedup vs baseline: 3.2762x; 1.7632x over previous
#include <cuda_runtime.h>
#include <cuda_bf16.h>
#include <mma.h>
#include <math.h>
#include <stdint.h>

using namespace nvcuda;

// ---------------------------------------------------------------------------
// R-NEM cell on tensor cores (wmma bf16 HMMA; tcgen05 unavailable: harness
// PTX target is compute_103 without the 'a' suffix).
// fp32 emulated as bf16 hi/lo 3-term: D = AhBh + AhBl + AlBh, fp32 accum.
// R6: activations kept in bf16 hi/lo format end-to-end; A/B staging is pure
//     16B cp.async with a 2-stage pipeline (prefetch c+1 during mma of c).
// ---------------------------------------------------------------------------

#define EPS_LN 1e-5f

static constexpr int Bn  = 2048;
static constexpr int Kn  = 8;
static constexpr int BK  = Bn * Kn;          // 16384 entity rows
static constexpr int RR  = BK * (Kn - 1);    // 114688 pair rows
static constexpr int H1  = 250;
static constexpr int Mx  = 576;

// fp32 scratch (effect path only)
__device__ float g_ctx[RR * H1];
__device__ float g_att[RR];

// bf16 hi/lo activations (k-padded to chunk multiples, zero-filled pad)
__device__ __nv_bfloat16 g_sta_h[BK * 256], g_sta_l[BK * 256];
__device__ __nv_bfloat16 g_x_h  [BK * 576], g_x_l  [BK * 576];
__device__ __nv_bfloat16 g_s1_h [BK * 256], g_s1_l [BK * 256];
__device__ __nv_bfloat16 g_co_h [RR * 256], g_co_l [RR * 256];
__device__ __nv_bfloat16 g_ef_h [BK * 256], g_ef_l [BK * 256];

// Pre-split weights, layout [Kpad][NT] row-major; K remapped so each logical
// 250-wide segment is padded to 256 (chunk-aligned concat boundaries).
__device__ __nv_bfloat16 g_enc_h [256 * 256],  g_enc_l [256 * 256];
__device__ __nv_bfloat16 g_core_h[512 * 256],  g_core_l[512 * 256];
__device__ __nv_bfloat16 g_ctx_h [256 * 256],  g_ctx_l [256 * 256];
__device__ __nv_bfloat16 g_att_h [256 * 128],  g_att_l [256 * 128];
__device__ __nv_bfloat16 g_out_h [1088 * 256], g_out_l [1088 * 256];

// ---------------- cp.async helpers ----------------
__device__ __forceinline__ void cp16(uint32_t dst, const void* src) {
    asm volatile("cp.async.cg.shared.global [%0], [%1], 16;"
                 :: "r"(dst), "l"(src));
}
#define CP_COMMIT() asm volatile("cp.async.commit_group;" ::: "memory")
#define CP_WAIT1()  asm volatile("cp.async.wait_group 1;" ::: "memory")
#define CP_WAIT0()  asm volatile("cp.async.wait_group 0;" ::: "memory")

__device__ __forceinline__ uint32_t smem_u32(const void* p) {
    uint32_t a;
    asm("{ .reg .u64 t; cvta.to.shared.u64 t, %1; cvt.u32.u64 %0, t; }"
        : "=r"(a) : "l"(p));
    return a;
}

// ---------------- weight prep: remap K into padded segments, split ---------
// kpad < 512: segment kpad>>8 (each 250 valid of 256); kpad >= 512: x block.
__global__ __launch_bounds__(256)
void prep_w(const float* __restrict__ W, int Ksrc, int N, int NT, int Kpad,
            __nv_bfloat16* __restrict__ bh, __nv_bfloat16* __restrict__ bl)
{
    int idx = blockIdx.x * 256 + threadIdx.x;
    if (idx >= Kpad * NT) return;
    int kpad = idx / NT;
    int n    = idx - kpad * NT;
    int ksrc; bool valid;
    if (kpad < 512) {
        int seg = kpad >> 8, w = kpad & 255;
        ksrc = seg * 250 + w;
        valid = (w < 250) && (ksrc < Ksrc);
    } else {
        ksrc = 500 + (kpad - 512);
        valid = ksrc < Ksrc;
    }
    float v = (valid && n < N) ? W[ksrc * N + n] : 0.f;
    __nv_bfloat16 h = __float2bfloat16(v);
    bh[idx] = h;
    bl[idx] = __float2bfloat16(v - __bfloat162float(h));
}

// fp32 [rows][W] -> bf16 hi/lo [rows][Wp], zero pad
__global__ __launch_bounds__(256)
void prep_split(const float* __restrict__ src, int W, int Wp, int rows,
                __nv_bfloat16* __restrict__ h, __nv_bfloat16* __restrict__ l)
{
    int idx = blockIdx.x * 256 + threadIdx.x;
    if (idx >= rows * Wp) return;
    int r = idx / Wp;
    int c = idx - r * Wp;
    float v = (c < W) ? src[(size_t)r * W + c] : 0.f;
    __nv_bfloat16 hh = __float2bfloat16(v);
    h[idx] = hh;
    l[idx] = __float2bfloat16(v - __bfloat162float(hh));
}

// ---------------- fused wmma GEMM ------------------------------------------
// NT: padded N (256 / 128). N: logical cols. KDIM: padded K (mult of 64).
// ASRC: 0 direct (src width = KDIM), 1 pair-concat of s1 (256+256),
//       2 tri-concat (s1 256 | eff 256 | x 576).
// ACT: 0 relu, 1 tanh, 2 none.
// OUT: 0 fp32 C, 1 bf16 hi/lo (width NT, zero pad), 2 attention scalar.
template <int NT, int N, int KDIM, int ASRC, int ACT, bool DO_LN, int OUT>
__global__ __launch_bounds__(256, 1)
void tc_gemm(const __nv_bfloat16* __restrict__ Ah, const __nv_bfloat16* __restrict__ Al,
             const __nv_bfloat16* __restrict__ A2h, const __nv_bfloat16* __restrict__ A2l,
             const __nv_bfloat16* __restrict__ A3h, const __nv_bfloat16* __restrict__ A3l,
             const __nv_bfloat16* __restrict__ Bh, const __nv_bfloat16* __restrict__ Bl,
             const float* __restrict__ bias, const float* __restrict__ gamma,
             const float* __restrict__ beta, const float* __restrict__ W2,
             const float* __restrict__ b2,
             float* __restrict__ Cf, __nv_bfloat16* __restrict__ Ch,
             __nv_bfloat16* __restrict__ Cl, int ldc)
{
    constexpr int KC   = KDIM / 64;
    constexpr int LDA  = 72;                 // elems (144B rows: bank rotation)
    constexpr int LDB  = NT + 8;
    constexpr int CLD  = NT + 8;
    constexpr int A_BYTES = 128 * LDA * 2;   // one matrix (h or l)
    constexpr int B_BYTES = 64 * LDB * 2;
    constexpr int STG  = 2 * A_BYTES + 2 * B_BYTES;
    constexpr int WN   = NT / 64;
    constexpr int WM   = 8 / WN;
    constexpr int MROW = 128 / WM;
    constexpr int MF   = MROW / 16;
    constexpr int NF   = 4;

    extern __shared__ char smem[];
    const uint32_t sb = smem_u32(smem);
    int* srcF = (int*)(smem + 2 * STG);
    int* srcC = srcF + 128;

    const int tid = threadIdx.x;
    const int wid = tid >> 5;
    const int rowBase = blockIdx.x * 128;

    if (ASRC == 1) {
        if (tid < 128) {
            int r    = rowBase + tid;
            int bidx = r / (Kn * (Kn - 1));
            int rem  = r - bidx * (Kn * (Kn - 1));
            int i    = rem / (Kn - 1);
            int jj   = rem - i * (Kn - 1);
            int j    = jj + (jj >= i ? 1 : 0);   // idx[i] = [0..K-1] \ {i}
            srcF[tid] = bidx * Kn + i;
            srcC[tid] = bidx * Kn + j;
        }
        __syncthreads();
    }

    // ---- async stage of one 64-k chunk (A h/l + B h/l, pure 16B copies) ----
    auto stage = [&](int c) {
        const int st = c & 1;
        const uint32_t ah = sb + st * STG;
        const uint32_t al = ah + A_BYTES;
        const uint32_t bh = al + A_BYTES;
        const uint32_t bl = bh + B_BYTES;
        #pragma unroll
        for (int i = 0; i < 4; ++i) {              // 1024 A-units per matrix
            int u   = tid + i * 256;
            int row = u >> 3, k16 = u & 7;
            const __nv_bfloat16 *sh, *sl;
            int off;
            if (ASRC == 0) {
                size_t r = (size_t)(rowBase + row);
                sh = Ah + r * KDIM; sl = Al + r * KDIM;
                off = c * 64 + k16 * 8;
            } else if (ASRC == 1) {
                size_t rr = (size_t)((c < 4) ? srcF[row] : srcC[row]);
                sh = Ah + rr * 256; sl = Al + rr * 256;
                off = ((c < 4) ? c : c - 4) * 64 + k16 * 8;
            } else {
                size_t r = (size_t)(rowBase + row);
                if (c < 4)      { sh = Ah  + r * 256; sl = Al  + r * 256; off = c * 64 + k16 * 8; }
                else if (c < 8) { sh = A2h + r * 256; sl = A2l + r * 256; off = (c - 4) * 64 + k16 * 8; }
                else            { sh = A3h + r * 576; sl = A3l + r * 576; off = (c - 8) * 64 + k16 * 8; }
            }
            uint32_t d = (uint32_t)(row * (LDA * 2) + k16 * 16);
            cp16(ah + d, sh + off);
            cp16(al + d, sl + off);
        }
        #pragma unroll
        for (int i = 0; i < NT / 32; ++i) {        // 64*(NT/8) B-units / 256
            int u   = tid + i * 256;
            int kk  = u / (NT / 8), n16 = u % (NT / 8);
            size_t go = (size_t)(c * 64 + kk) * NT + n16 * 8;
            uint32_t d = (uint32_t)(kk * (LDB * 2) + n16 * 16);
            cp16(bh + d, Bh + go);
            cp16(bl + d, Bl + go);
        }
    };

    const int wm = wid / WN, wn = wid % WN;
    const int mrow0 = wm * MROW, ncol0 = wn * 64;

    wmma::fragment<wmma::accumulator, 16, 16, 16, float> acc[MF][NF];
    #pragma unroll
    for (int i = 0; i < MF; ++i)
        #pragma unroll
        for (int j = 0; j < NF; ++j)
            wmma::fill_fragment(acc[i][j], 0.f);

    stage(0); CP_COMMIT();

    for (int c = 0; c < KC; ++c) {
        if (c + 1 < KC) { stage(c + 1); CP_COMMIT(); CP_WAIT1(); }
        else            { CP_WAIT0(); }
        __syncthreads();

        const int st = c & 1;
        const __nv_bfloat16* Ash = (const __nv_bfloat16*)(smem + st * STG);
        const __nv_bfloat16* Asl = Ash + 128 * LDA;
        const __nv_bfloat16* Bsh = Asl + 128 * LDA;
        const __nv_bfloat16* Bsl = Bsh + 64 * LDB;

        #pragma unroll
        for (int s = 0; s < 4; ++s) {
            wmma::fragment<wmma::matrix_a, 16, 16, 16, __nv_bfloat16, wmma::row_major> ah[MF], al[MF];
            #pragma unroll
            for (int i = 0; i < MF; ++i) {
                wmma::load_matrix_sync(ah[i], Ash + (mrow0 + i * 16) * LDA + s * 16, LDA);
                wmma::load_matrix_sync(al[i], Asl + (mrow0 + i * 16) * LDA + s * 16, LDA);
            }
            #pragma unroll
            for (int j = 0; j < NF; ++j) {
                wmma::fragment<wmma::matrix_b, 16, 16, 16, __nv_bfloat16, wmma::row_major> bh, bl;
                wmma::load_matrix_sync(bh, Bsh + (s * 16) * LDB + ncol0 + j * 16, LDB);
                wmma::load_matrix_sync(bl, Bsl + (s * 16) * LDB + ncol0 + j * 16, LDB);
                #pragma unroll
                for (int i = 0; i < MF; ++i) {
                    wmma::mma_sync(acc[i][j], ah[i], bh, acc[i][j]);
                    wmma::mma_sync(acc[i][j], ah[i], bl, acc[i][j]);
                    wmma::mma_sync(acc[i][j], al[i], bh, acc[i][j]);
                }
            }
        }
        __syncthreads();
    }

    // ---- dump accumulators to SMEM fp32 ----
    float* Cs = (float*)smem;
    #pragma unroll
    for (int i = 0; i < MF; ++i)
        #pragma unroll
        for (int j = 0; j < NF; ++j)
            wmma::store_matrix_sync(Cs + (mrow0 + i * 16) * CLD + ncol0 + j * 16,
                                    acc[i][j], CLD, wmma::mem_row_major);
    __syncthreads();

    constexpr int HC = NT / 2;
    float* muS  = (float*)(smem + 128 * CLD * 4);
    float* invS = muS + 128;

    if constexpr (OUT == 2) {
        // attention scalar: 2 threads per row, LN + dot fully in registers
        const int row = tid >> 1, hf = tid & 1;
        const float* crow = Cs + row * CLD + hf * HC;
        float sum = 0.f, ssq = 0.f;
        #pragma unroll 4
        for (int j = 0; j < HC; ++j) {
            int cc = hf * HC + j;
            float v = 0.f;
            if (cc < N) { v = tanhf(crow[j] + bias[cc]); }
            sum += v; ssq += v * v;
        }
        float s = sum + __shfl_xor_sync(0xffffffffu, sum, 1);
        float q = ssq + __shfl_xor_sync(0xffffffffu, ssq, 1);
        float mu = s / (float)N;
        float inv = rsqrtf(q / (float)N - mu * mu + EPS_LN);
        float d = 0.f;
        #pragma unroll 4
        for (int j = 0; j < HC; ++j) {
            int cc = hf * HC + j;
            if (cc < N) {
                float v = tanhf(crow[j] + bias[cc]);
                v = (v - mu) * inv * gamma[cc] + beta[cc];
                d += v * W2[cc];
            }
        }
        d += __shfl_xor_sync(0xffffffffu, d, 1);
        if (hf == 0) {
            float z = d + b2[0];
            Cf[rowBase + row] = 1.f / (1.f + expf(-z));
        }
    } else {
        if constexpr (DO_LN) {
            const int row = tid >> 1, hf = tid & 1;
            const float* crow = Cs + row * CLD + hf * HC;
            float sum = 0.f, ssq = 0.f;
            #pragma unroll 4
            for (int j = 0; j < HC; ++j) {
                int cc = hf * HC + j;
                float v = 0.f;
                if (cc < N) {
                    v = crow[j] + bias[cc];
                    if (ACT == 0)      v = fmaxf(v, 0.f);
                    else if (ACT == 1) v = tanhf(v);
                }
                sum += v; ssq += v * v;
            }
            float s = sum + __shfl_xor_sync(0xffffffffu, sum, 1);
            float q = ssq + __shfl_xor_sync(0xffffffffu, ssq, 1);
            if (hf == 0) {
                float mu = s / (float)N;
                muS[row]  = mu;
                invS[row] = rsqrtf(q / (float)N - mu * mu + EPS_LN);
            }
            __syncthreads();
        }
        // coalesced sweep, 2 cols per thread
        for (int e = tid * 2; e < 128 * NT; e += 512) {
            int row = e / NT;
            int col = e - row * NT;
            float mu = 0.f, iv = 0.f;
            if (DO_LN) { mu = muS[row]; iv = invS[row]; }
            float v[2];
            #pragma unroll
            for (int t = 0; t < 2; ++t) {
                int cc = col + t;
                float x = 0.f;
                if (cc < N) {
                    x = Cs[row * CLD + cc] + bias[cc];
                    if (ACT == 0)      x = fmaxf(x, 0.f);
                    else if (ACT == 1) x = tanhf(x);
                    if (DO_LN)
                        x = (x - mu) * iv * gamma[cc] + beta[cc];
                }
                v[t] = x;
            }
            if (OUT == 1) {
                __nv_bfloat16 h0 = __float2bfloat16(v[0]);
                __nv_bfloat16 h1 = __float2bfloat16(v[1]);
                __nv_bfloat16 l0 = __float2bfloat16(v[0] - __bfloat162float(h0));
                __nv_bfloat16 l1 = __float2bfloat16(v[1] - __bfloat162float(h1));
                size_t o = (size_t)(rowBase + row) * NT + col;
                *(__nv_bfloat162*)(Ch + o) = __nv_bfloat162(h0, h1);
                *(__nv_bfloat162*)(Cl + o) = __nv_bfloat162(l0, l1);
            } else {
                size_t o = (size_t)(rowBase + row) * ldc + col;
                if (col < N)     Cf[o]     = v[0];
                if (col + 1 < N) Cf[o + 1] = v[1];
            }
        }
    }
}

// eff[bk, c] = sum_{j<7} ctx[bk*7+j, c] * att[bk*7+j]; emit bf16 hi/lo pad-256
__global__ __launch_bounds__(256)
void effect_kernel(const float* __restrict__ ctx,
                   const float* __restrict__ att,
                   __nv_bfloat16* __restrict__ effh,
                   __nv_bfloat16* __restrict__ effl)
{
    const int bk = blockIdx.x;
    __shared__ float a[Kn - 1];
    if (threadIdx.x < Kn - 1) a[threadIdx.x] = att[bk * (Kn - 1) + threadIdx.x];
    __syncthreads();
    int c = threadIdx.x;
    float s = 0.f;
    if (c < H1) {
        const float* base = ctx + (size_t)bk * (Kn - 1) * H1;
        #pragma unroll
        for (int j = 0; j < Kn - 1; ++j)
            s = fmaf(base[j * H1 + c], a[j], s);
    }
    __nv_bfloat16 h = __float2bfloat16(s);
    effh[(size_t)bk * 256 + c] = h;
    effl[(size_t)bk * 256 + c] = __float2bfloat16(s - __bfloat162float(h));
}

extern "C" void kernel_launch(void* const* d_in, const int* in_sizes, int n_in,
                              void* d_out, int out_size)
{
    const float* x      = (const float*)d_in[0];
    const float* state  = (const float*)d_in[1];
    const float* enc_W  = (const float*)d_in[2];
    const float* enc_b  = (const float*)d_in[3];
    const float* enc_g  = (const float*)d_in[4];
    const float* enc_bt = (const float*)d_in[5];
    const float* core_W = (const float*)d_in[6];
    const float* core_b = (const float*)d_in[7];
    const float* core_g = (const float*)d_in[8];
    const float* core_bt= (const float*)d_in[9];
    const float* ctx_W  = (const float*)d_in[10];
    const float* ctx_b  = (const float*)d_in[11];
    const float* ctx_g  = (const float*)d_in[12];
    const float* ctx_bt = (const float*)d_in[13];
    const float* att_W1 = (const float*)d_in[14];
    const float* att_b1 = (const float*)d_in[15];
    const float* att_g  = (const float*)d_in[16];
    const float* att_bt = (const float*)d_in[17];
    const float* att_W2 = (const float*)d_in[18];
    const float* att_b2 = (const float*)d_in[19];
    const float* out_W  = (const float*)d_in[20];
    const float* out_b  = (const float*)d_in[21];
    float* out = (float*)d_out;

    float *p_ctx, *p_att;
    cudaGetSymbolAddress((void**)&p_ctx, g_ctx);
    cudaGetSymbolAddress((void**)&p_att, g_att);

    __nv_bfloat16 *stah, *stal, *xh, *xl, *s1h, *s1l, *coh, *col_, *efh, *efl;
    cudaGetSymbolAddress((void**)&stah, g_sta_h); cudaGetSymbolAddress((void**)&stal, g_sta_l);
    cudaGetSymbolAddress((void**)&xh,   g_x_h);   cudaGetSymbolAddress((void**)&xl,   g_x_l);
    cudaGetSymbolAddress((void**)&s1h,  g_s1_h);  cudaGetSymbolAddress((void**)&s1l,  g_s1_l);
    cudaGetSymbolAddress((void**)&coh,  g_co_h);  cudaGetSymbolAddress((void**)&col_, g_co_l);
    cudaGetSymbolAddress((void**)&efh,  g_ef_h);  cudaGetSymbolAddress((void**)&efl,  g_ef_l);

    __nv_bfloat16 *ench, *encl, *corh, *corl, *ctxh, *ctxl, *atth, *attl, *outh, *outl;
    cudaGetSymbolAddress((void**)&ench, g_enc_h);  cudaGetSymbolAddress((void**)&encl, g_enc_l);
    cudaGetSymbolAddress((void**)&corh, g_core_h); cudaGetSymbolAddress((void**)&corl, g_core_l);
    cudaGetSymbolAddress((void**)&ctxh, g_ctx_h);  cudaGetSymbolAddress((void**)&ctxl, g_ctx_l);
    cudaGetSymbolAddress((void**)&atth, g_att_h);  cudaGetSymbolAddress((void**)&attl, g_att_l);
    cudaGetSymbolAddress((void**)&outh, g_out_h);  cudaGetSymbolAddress((void**)&outl, g_out_l);

    // SMEM: 2 stages x (2*A + 2*B) + 1KB src indices
    constexpr int SM256 = 2 * (2 * 128 * 72 * 2 + 2 * 64 * 264 * 2) + 1024; // 209920
    constexpr int SM128 = 2 * (2 * 128 * 72 * 2 + 2 * 64 * 136 * 2) + 1024; // 144384
    cudaFuncSetAttribute(tc_gemm<256, 250, 256,  0, 0, true,  1>,
                         cudaFuncAttributeMaxDynamicSharedMemorySize, SM256);
    cudaFuncSetAttribute(tc_gemm<256, 250, 512,  1, 0, true,  1>,
                         cudaFuncAttributeMaxDynamicSharedMemorySize, SM256);
    cudaFuncSetAttribute(tc_gemm<256, 250, 256,  0, 0, true,  0>,
                         cudaFuncAttributeMaxDynamicSharedMemorySize, SM256);
    cudaFuncSetAttribute(tc_gemm<128, 100, 256,  0, 1, true,  2>,
                         cudaFuncAttributeMaxDynamicSharedMemorySize, SM128);
    cudaFuncSetAttribute(tc_gemm<256, 250, 1088, 2, 2, false, 0>,
                         cudaFuncAttributeMaxDynamicSharedMemorySize, SM256);

    // --- weight prep (segment-remapped K, hi/lo split) ---
    prep_w<<<(256  * 256 + 255) / 256, 256>>>(enc_W,  250,  250, 256, 256,  ench, encl);
    prep_w<<<(512  * 256 + 255) / 256, 256>>>(core_W, 500,  250, 256, 512,  corh, corl);
    prep_w<<<(256  * 256 + 255) / 256, 256>>>(ctx_W,  250,  250, 256, 256,  ctxh, ctxl);
    prep_w<<<(256  * 128 + 255) / 256, 256>>>(att_W1, 250,  100, 128, 256,  atth, attl);
    prep_w<<<(1088 * 256 + 255) / 256, 256>>>(out_W,  1076, 250, 256, 1088, outh, outl);

    // --- activation input prep ---
    prep_split<<<(BK * 256 + 255) / 256, 256>>>(state, 250, 256, BK, stah, stal);
    prep_split<<<(BK * 576 + 255) / 256, 256>>>(x,     576, 576, BK, xh,   xl);

    // s1 = LN(relu(state @ enc_W + b))  -> bf16 hi/lo
    tc_gemm<256, 250, 256, 0, 0, true, 1><<<BK / 128, 256, SM256>>>(
        stah, stal, nullptr, nullptr, nullptr, nullptr, ench, encl,
        enc_b, enc_g, enc_bt, nullptr, nullptr, nullptr, s1h, s1l, 0);

    // core = LN(relu(concat(fs,cs) @ core_W + b)) -> bf16 hi/lo
    tc_gemm<256, 250, 512, 1, 0, true, 1><<<RR / 128, 256, SM256>>>(
        s1h, s1l, nullptr, nullptr, nullptr, nullptr, corh, corl,
        core_b, core_g, core_bt, nullptr, nullptr, nullptr, coh, col_, 0);

    // ctx = LN(relu(core @ ctx_W + b)) -> fp32 (effect consumes)
    tc_gemm<256, 250, 256, 0, 0, true, 0><<<RR / 128, 256, SM256>>>(
        coh, col_, nullptr, nullptr, nullptr, nullptr, ctxh, ctxl,
        ctx_b, ctx_g, ctx_bt, nullptr, nullptr, p_ctx, nullptr, nullptr, H1);

    // att = sigmoid(LN(tanh(core @ att_W1 + b1)) @ att_W2 + b2)
    tc_gemm<128, 100, 256, 0, 1, true, 2><<<RR / 128, 256, SM128>>>(
        coh, col_, nullptr, nullptr, nullptr, nullptr, atth, attl,
        att_b1, att_g, att_bt, att_W2, att_b2, p_att, nullptr, nullptr, 0);

    // eff = 7-way attention-weighted reduction of ctx -> bf16 hi/lo
    effect_kernel<<<BK, 256>>>(p_ctx, p_att, efh, efl);

    // out = concat(s1, eff, x) @ out_W + out_b -> fp32 d_out
    tc_gemm<256, 250, 1088, 2, 2, false, 0><<<BK / 128, 256, SM256>>>(
        s1h, s1l, efh, efl, xh, xl, outh, outl,
        out_b, nullptr, nullptr, nullptr, nullptr, out, nullptr, nullptr, H1);
}

// round 8
// speedup vs baseline: 3.9885x; 1.2174x over previous
#include <cuda_runtime.h>
#include <cuda_bf16.h>
#include <mma.h>
#include <math.h>
#include <stdint.h>

using namespace nvcuda;

// ---------------------------------------------------------------------------
// R-NEM cell on tensor cores (wmma bf16 HMMA; tcgen05 unavailable on the
// harness's compute_103 PTX target). fp32 emulated as bf16 hi/lo 3-term.
// R7: core GEMM decomposed — concat(fs,cs)@W == F[b,i] + G[b,j] with
//     F = s1@W_top, G = s1@W_bot over 16384 entity rows instead of 114688
//     pair rows (-40% total math). Pair-combine is a cheap elementwise+LN
//     kernel emitting bf16 hi/lo.
// ---------------------------------------------------------------------------

#define EPS_LN 1e-5f

static constexpr int Bn  = 2048;
static constexpr int Kn  = 8;
static constexpr int BK  = Bn * Kn;          // 16384 entity rows
static constexpr int RR  = BK * (Kn - 1);    // 114688 pair rows
static constexpr int H1  = 250;
static constexpr int Mx  = 576;

// fp32 scratch
__device__ float g_F  [BK * 256];
__device__ float g_G  [BK * 256];
__device__ float g_ctx[RR * H1];
__device__ float g_att[RR];
__device__ float g_zeros[256];               // zero bias for F/G GEMMs

// bf16 hi/lo activations (k-padded, zero-filled pad)
__device__ __nv_bfloat16 g_sta_h[BK * 256], g_sta_l[BK * 256];
__device__ __nv_bfloat16 g_x_h  [BK * 576], g_x_l  [BK * 576];
__device__ __nv_bfloat16 g_s1_h [BK * 256], g_s1_l [BK * 256];
__device__ __nv_bfloat16 g_co_h [RR * 256], g_co_l [RR * 256];
__device__ __nv_bfloat16 g_ef_h [BK * 256], g_ef_l [BK * 256];

// Pre-split weights, [Kpad][NT] row-major; 250-wide K segments padded to 256.
__device__ __nv_bfloat16 g_enc_h [256 * 256],  g_enc_l [256 * 256];
__device__ __nv_bfloat16 g_wtop_h[256 * 256],  g_wtop_l[256 * 256];
__device__ __nv_bfloat16 g_wbot_h[256 * 256],  g_wbot_l[256 * 256];
__device__ __nv_bfloat16 g_ctx_h [256 * 256],  g_ctx_l [256 * 256];
__device__ __nv_bfloat16 g_att_h [256 * 128],  g_att_l [256 * 128];
__device__ __nv_bfloat16 g_out_h [1088 * 256], g_out_l [1088 * 256];

// ---------------- cp.async helpers ----------------
__device__ __forceinline__ void cp16(uint32_t dst, const void* src) {
    asm volatile("cp.async.cg.shared.global [%0], [%1], 16;"
                 :: "r"(dst), "l"(src));
}
#define CP_COMMIT() asm volatile("cp.async.commit_group;" ::: "memory")
#define CP_WAIT1()  asm volatile("cp.async.wait_group 1;" ::: "memory")
#define CP_WAIT0()  asm volatile("cp.async.wait_group 0;" ::: "memory")

__device__ __forceinline__ uint32_t smem_u32(const void* p) {
    uint32_t a;
    asm("{ .reg .u64 t; cvta.to.shared.u64 t, %1; cvt.u32.u64 %0, t; }"
        : "=r"(a) : "l"(p));
    return a;
}

__device__ __forceinline__ float warp_sum32(float v) {
    v += __shfl_xor_sync(0xffffffffu, v, 16);
    v += __shfl_xor_sync(0xffffffffu, v, 8);
    v += __shfl_xor_sync(0xffffffffu, v, 4);
    v += __shfl_xor_sync(0xffffffffu, v, 2);
    v += __shfl_xor_sync(0xffffffffu, v, 1);
    return v;
}

// ---------------- weight prep: remap K into padded segments, split ---------
__global__ __launch_bounds__(256)
void prep_w(const float* __restrict__ W, int Ksrc, int N, int NT, int Kpad,
            __nv_bfloat16* __restrict__ bh, __nv_bfloat16* __restrict__ bl)
{
    int idx = blockIdx.x * 256 + threadIdx.x;
    if (idx >= Kpad * NT) return;
    int kpad = idx / NT;
    int n    = idx - kpad * NT;
    int ksrc; bool valid;
    if (kpad < 512) {
        int seg = kpad >> 8, w = kpad & 255;
        ksrc = seg * 250 + w;
        valid = (w < 250) && (ksrc < Ksrc);
    } else {
        ksrc = 500 + (kpad - 512);
        valid = ksrc < Ksrc;
    }
    float v = (valid && n < N) ? W[ksrc * N + n] : 0.f;
    __nv_bfloat16 h = __float2bfloat16(v);
    bh[idx] = h;
    bl[idx] = __float2bfloat16(v - __bfloat162float(h));
}

// fp32 [rows][W] -> bf16 hi/lo [rows][Wp], zero pad
__global__ __launch_bounds__(256)
void prep_split(const float* __restrict__ src, int W, int Wp, int rows,
                __nv_bfloat16* __restrict__ h, __nv_bfloat16* __restrict__ l)
{
    int idx = blockIdx.x * 256 + threadIdx.x;
    if (idx >= rows * Wp) return;
    int r = idx / Wp;
    int c = idx - r * Wp;
    float v = (c < W) ? src[(size_t)r * W + c] : 0.f;
    __nv_bfloat16 hh = __float2bfloat16(v);
    h[idx] = hh;
    l[idx] = __float2bfloat16(v - __bfloat162float(hh));
}

// ---------------- pair combine: core = LN(relu(F[b,i]+G[b,j]+b)) -----------
// 8 rows per block, one warp per row; lane owns 8 contiguous cols.
__global__ __launch_bounds__(256)
void combine_kernel(const float* __restrict__ F, const float* __restrict__ G,
                    const float* __restrict__ bias,
                    const float* __restrict__ gamma,
                    const float* __restrict__ beta,
                    __nv_bfloat16* __restrict__ coh,
                    __nv_bfloat16* __restrict__ col_)
{
    const int r    = blockIdx.x * 8 + (threadIdx.x >> 5);
    const int lane = threadIdx.x & 31;

    int bidx = r / (Kn * (Kn - 1));
    int rem  = r - bidx * (Kn * (Kn - 1));
    int i    = rem / (Kn - 1);
    int jj   = rem - i * (Kn - 1);
    int j    = jj + (jj >= i ? 1 : 0);

    const float* fr = F + (size_t)(bidx * Kn + i) * 256 + lane * 8;
    const float* gr = G + (size_t)(bidx * Kn + j) * 256 + lane * 8;

    float4 f0 = *(const float4*)(fr);
    float4 f1 = *(const float4*)(fr + 4);
    float4 g0 = *(const float4*)(gr);
    float4 g1 = *(const float4*)(gr + 4);

    float v[8];
    {
        const float* fa = &f0.x; const float* ga = &g0.x;
        #pragma unroll
        for (int t = 0; t < 4; ++t) {
            int c = lane * 8 + t;
            v[t] = (c < H1) ? fmaxf(fa[t] + ga[t] + bias[c], 0.f) : 0.f;
        }
        const float* fb = &f1.x; const float* gb = &g1.x;
        #pragma unroll
        for (int t = 0; t < 4; ++t) {
            int c = lane * 8 + 4 + t;
            v[4 + t] = (c < H1) ? fmaxf(fb[t] + gb[t] + bias[c], 0.f) : 0.f;
        }
    }

    float sum = 0.f, ssq = 0.f;
    #pragma unroll
    for (int t = 0; t < 8; ++t) { sum += v[t]; ssq += v[t] * v[t]; }
    sum = warp_sum32(sum);
    ssq = warp_sum32(ssq);
    float mu  = sum / (float)H1;
    float inv = rsqrtf(ssq / (float)H1 - mu * mu + EPS_LN);

    size_t o = (size_t)r * 256 + lane * 8;
    #pragma unroll
    for (int t = 0; t < 8; t += 2) {
        int c0 = lane * 8 + t, c1 = c0 + 1;
        float y0 = (c0 < H1) ? (v[t]     - mu) * inv * gamma[c0] + beta[c0] : 0.f;
        float y1 = (c1 < H1) ? (v[t + 1] - mu) * inv * gamma[c1] + beta[c1] : 0.f;
        __nv_bfloat16 h0 = __float2bfloat16(y0);
        __nv_bfloat16 h1 = __float2bfloat16(y1);
        __nv_bfloat16 l0 = __float2bfloat16(y0 - __bfloat162float(h0));
        __nv_bfloat16 l1 = __float2bfloat16(y1 - __bfloat162float(h1));
        *(__nv_bfloat162*)(coh  + o + t) = __nv_bfloat162(h0, h1);
        *(__nv_bfloat162*)(col_ + o + t) = __nv_bfloat162(l0, l1);
    }
}

// ---------------- fused wmma GEMM ------------------------------------------
// NT: padded N (256 / 128). N: logical cols. KDIM: padded K (mult of 64).
// ASRC: 0 direct (src width = KDIM), 2 tri-concat (s1 256 | eff 256 | x 576).
// ACT: 0 relu, 1 tanh, 2 none.
// OUT: 0 fp32 C, 1 bf16 hi/lo (width NT, zero pad), 2 attention scalar.
template <int NT, int N, int KDIM, int ASRC, int ACT, bool DO_LN, int OUT>
__global__ __launch_bounds__(256, 1)
void tc_gemm(const __nv_bfloat16* __restrict__ Ah, const __nv_bfloat16* __restrict__ Al,
             const __nv_bfloat16* __restrict__ A2h, const __nv_bfloat16* __restrict__ A2l,
             const __nv_bfloat16* __restrict__ A3h, const __nv_bfloat16* __restrict__ A3l,
             const __nv_bfloat16* __restrict__ Bh, const __nv_bfloat16* __restrict__ Bl,
             const float* __restrict__ bias, const float* __restrict__ gamma,
             const float* __restrict__ beta, const float* __restrict__ W2,
             const float* __restrict__ b2,
             float* __restrict__ Cf, __nv_bfloat16* __restrict__ Ch,
             __nv_bfloat16* __restrict__ Cl, int ldc)
{
    constexpr int KC   = KDIM / 64;
    constexpr int LDA  = 72;                 // elems (144B rows: bank rotation)
    constexpr int LDB  = NT + 8;
    constexpr int CLD  = NT + 8;
    constexpr int A_BYTES = 128 * LDA * 2;
    constexpr int B_BYTES = 64 * LDB * 2;
    constexpr int STG  = 2 * A_BYTES + 2 * B_BYTES;
    constexpr int WN   = NT / 64;
    constexpr int WM   = 8 / WN;
    constexpr int MROW = 128 / WM;
    constexpr int MF   = MROW / 16;
    constexpr int NF   = 4;

    extern __shared__ char smem[];
    const uint32_t sb = smem_u32(smem);

    const int tid = threadIdx.x;
    const int wid = tid >> 5;
    const int rowBase = blockIdx.x * 128;

    // ---- async stage of one 64-k chunk (A h/l + B h/l, pure 16B copies) ----
    auto stage = [&](int c) {
        const int st = c & 1;
        const uint32_t ah = sb + st * STG;
        const uint32_t al = ah + A_BYTES;
        const uint32_t bh = al + A_BYTES;
        const uint32_t bl = bh + B_BYTES;
        #pragma unroll
        for (int i = 0; i < 4; ++i) {              // 1024 A-units per matrix
            int u   = tid + i * 256;
            int row = u >> 3, k16 = u & 7;
            const __nv_bfloat16 *sh, *sl;
            int off;
            size_t r = (size_t)(rowBase + row);
            if (ASRC == 0) {
                sh = Ah + r * KDIM; sl = Al + r * KDIM;
                off = c * 64 + k16 * 8;
            } else {
                if (c < 4)      { sh = Ah  + r * 256; sl = Al  + r * 256; off = c * 64 + k16 * 8; }
                else if (c < 8) { sh = A2h + r * 256; sl = A2l + r * 256; off = (c - 4) * 64 + k16 * 8; }
                else            { sh = A3h + r * 576; sl = A3l + r * 576; off = (c - 8) * 64 + k16 * 8; }
            }
            uint32_t d = (uint32_t)(row * (LDA * 2) + k16 * 16);
            cp16(ah + d, sh + off);
            cp16(al + d, sl + off);
        }
        #pragma unroll
        for (int i = 0; i < NT / 32; ++i) {
            int u   = tid + i * 256;
            int kk  = u / (NT / 8), n16 = u % (NT / 8);
            size_t go = (size_t)(c * 64 + kk) * NT + n16 * 8;
            uint32_t d = (uint32_t)(kk * (LDB * 2) + n16 * 16);
            cp16(bh + d, Bh + go);
            cp16(bl + d, Bl + go);
        }
    };

    const int wm = wid / WN, wn = wid % WN;
    const int mrow0 = wm * MROW, ncol0 = wn * 64;

    wmma::fragment<wmma::accumulator, 16, 16, 16, float> acc[MF][NF];
    #pragma unroll
    for (int i = 0; i < MF; ++i)
        #pragma unroll
        for (int j = 0; j < NF; ++j)
            wmma::fill_fragment(acc[i][j], 0.f);

    stage(0); CP_COMMIT();

    for (int c = 0; c < KC; ++c) {
        if (c + 1 < KC) { stage(c + 1); CP_COMMIT(); CP_WAIT1(); }
        else            { CP_WAIT0(); }
        __syncthreads();

        const int st = c & 1;
        const __nv_bfloat16* Ash = (const __nv_bfloat16*)(smem + st * STG);
        const __nv_bfloat16* Asl = Ash + 128 * LDA;
        const __nv_bfloat16* Bsh = Asl + 128 * LDA;
        const __nv_bfloat16* Bsl = Bsh + 64 * LDB;

        #pragma unroll
        for (int s = 0; s < 4; ++s) {
            wmma::fragment<wmma::matrix_a, 16, 16, 16, __nv_bfloat16, wmma::row_major> ah[MF], al[MF];
            #pragma unroll
            for (int i = 0; i < MF; ++i) {
                wmma::load_matrix_sync(ah[i], Ash + (mrow0 + i * 16) * LDA + s * 16, LDA);
                wmma::load_matrix_sync(al[i], Asl + (mrow0 + i * 16) * LDA + s * 16, LDA);
            }
            #pragma unroll
            for (int j = 0; j < NF; ++j) {
                wmma::fragment<wmma::matrix_b, 16, 16, 16, __nv_bfloat16, wmma::row_major> bh, bl;
                wmma::load_matrix_sync(bh, Bsh + (s * 16) * LDB + ncol0 + j * 16, LDB);
                wmma::load_matrix_sync(bl, Bsl + (s * 16) * LDB + ncol0 + j * 16, LDB);
                #pragma unroll
                for (int i = 0; i < MF; ++i) {
                    wmma::mma_sync(acc[i][j], ah[i], bh, acc[i][j]);
                    wmma::mma_sync(acc[i][j], ah[i], bl, acc[i][j]);
                    wmma::mma_sync(acc[i][j], al[i], bh, acc[i][j]);
                }
            }
        }
        __syncthreads();
    }

    // ---- dump accumulators to SMEM fp32 ----
    float* Cs = (float*)smem;
    #pragma unroll
    for (int i = 0; i < MF; ++i)
        #pragma unroll
        for (int j = 0; j < NF; ++j)
            wmma::store_matrix_sync(Cs + (mrow0 + i * 16) * CLD + ncol0 + j * 16,
                                    acc[i][j], CLD, wmma::mem_row_major);
    __syncthreads();

    constexpr int HC = NT / 2;
    float* muS  = (float*)(smem + 128 * CLD * 4);
    float* invS = muS + 128;

    if constexpr (OUT == 2) {
        const int row = tid >> 1, hf = tid & 1;
        const float* crow = Cs + row * CLD + hf * HC;
        float sum = 0.f, ssq = 0.f;
        #pragma unroll 4
        for (int j = 0; j < HC; ++j) {
            int cc = hf * HC + j;
            float v = 0.f;
            if (cc < N) { v = tanhf(crow[j] + bias[cc]); }
            sum += v; ssq += v * v;
        }
        float s = sum + __shfl_xor_sync(0xffffffffu, sum, 1);
        float q = ssq + __shfl_xor_sync(0xffffffffu, ssq, 1);
        float mu = s / (float)N;
        float inv = rsqrtf(q / (float)N - mu * mu + EPS_LN);
        float d = 0.f;
        #pragma unroll 4
        for (int j = 0; j < HC; ++j) {
            int cc = hf * HC + j;
            if (cc < N) {
                float v = tanhf(crow[j] + bias[cc]);
                v = (v - mu) * inv * gamma[cc] + beta[cc];
                d += v * W2[cc];
            }
        }
        d += __shfl_xor_sync(0xffffffffu, d, 1);
        if (hf == 0) {
            float z = d + b2[0];
            Cf[rowBase + row] = 1.f / (1.f + expf(-z));
        }
    } else {
        if constexpr (DO_LN) {
            const int row = tid >> 1, hf = tid & 1;
            const float* crow = Cs + row * CLD + hf * HC;
            float sum = 0.f, ssq = 0.f;
            #pragma unroll 4
            for (int j = 0; j < HC; ++j) {
                int cc = hf * HC + j;
                float v = 0.f;
                if (cc < N) {
                    v = crow[j] + bias[cc];
                    if (ACT == 0)      v = fmaxf(v, 0.f);
                    else if (ACT == 1) v = tanhf(v);
                }
                sum += v; ssq += v * v;
            }
            float s = sum + __shfl_xor_sync(0xffffffffu, sum, 1);
            float q = ssq + __shfl_xor_sync(0xffffffffu, ssq, 1);
            if (hf == 0) {
                float mu = s / (float)N;
                muS[row]  = mu;
                invS[row] = rsqrtf(q / (float)N - mu * mu + EPS_LN);
            }
            __syncthreads();
        }
        for (int e = tid * 2; e < 128 * NT; e += 512) {
            int row = e / NT;
            int col = e - row * NT;
            float mu = 0.f, iv = 0.f;
            if (DO_LN) { mu = muS[row]; iv = invS[row]; }
            float v[2];
            #pragma unroll
            for (int t = 0; t < 2; ++t) {
                int cc = col + t;
                float xv = 0.f;
                if (cc < N) {
                    xv = Cs[row * CLD + cc] + bias[cc];
                    if (ACT == 0)      xv = fmaxf(xv, 0.f);
                    else if (ACT == 1) xv = tanhf(xv);
                    if (DO_LN)
                        xv = (xv - mu) * iv * gamma[cc] + beta[cc];
                }
                v[t] = xv;
            }
            if (OUT == 1) {
                __nv_bfloat16 h0 = __float2bfloat16(v[0]);
                __nv_bfloat16 h1 = __float2bfloat16(v[1]);
                __nv_bfloat16 l0 = __float2bfloat16(v[0] - __bfloat162float(h0));
                __nv_bfloat16 l1 = __float2bfloat16(v[1] - __bfloat162float(h1));
                size_t o = (size_t)(rowBase + row) * NT + col;
                *(__nv_bfloat162*)(Ch + o) = __nv_bfloat162(h0, h1);
                *(__nv_bfloat162*)(Cl + o) = __nv_bfloat162(l0, l1);
            } else {
                size_t o = (size_t)(rowBase + row) * ldc + col;
                if (col < N)     Cf[o]     = v[0];
                if (col + 1 < N) Cf[o + 1] = v[1];
            }
        }
    }
}

// eff[bk, c] = sum_{j<7} ctx[bk*7+j, c] * att[bk*7+j]; emit bf16 hi/lo pad-256
__global__ __launch_bounds__(256)
void effect_kernel(const float* __restrict__ ctx,
                   const float* __restrict__ att,
                   __nv_bfloat16* __restrict__ effh,
                   __nv_bfloat16* __restrict__ effl)
{
    const int bk = blockIdx.x;
    __shared__ float a[Kn - 1];
    if (threadIdx.x < Kn - 1) a[threadIdx.x] = att[bk * (Kn - 1) + threadIdx.x];
    __syncthreads();
    int c = threadIdx.x;
    float s = 0.f;
    if (c < H1) {
        const float* base = ctx + (size_t)bk * (Kn - 1) * H1;
        #pragma unroll
        for (int j = 0; j < Kn - 1; ++j)
            s = fmaf(base[j * H1 + c], a[j], s);
    }
    __nv_bfloat16 h = __float2bfloat16(s);
    effh[(size_t)bk * 256 + c] = h;
    effl[(size_t)bk * 256 + c] = __float2bfloat16(s - __bfloat162float(h));
}

extern "C" void kernel_launch(void* const* d_in, const int* in_sizes, int n_in,
                              void* d_out, int out_size)
{
    const float* x      = (const float*)d_in[0];
    const float* state  = (const float*)d_in[1];
    const float* enc_W  = (const float*)d_in[2];
    const float* enc_b  = (const float*)d_in[3];
    const float* enc_g  = (const float*)d_in[4];
    const float* enc_bt = (const float*)d_in[5];
    const float* core_W = (const float*)d_in[6];
    const float* core_b = (const float*)d_in[7];
    const float* core_g = (const float*)d_in[8];
    const float* core_bt= (const float*)d_in[9];
    const float* ctx_W  = (const float*)d_in[10];
    const float* ctx_b  = (const float*)d_in[11];
    const float* ctx_g  = (const float*)d_in[12];
    const float* ctx_bt = (const float*)d_in[13];
    const float* att_W1 = (const float*)d_in[14];
    const float* att_b1 = (const float*)d_in[15];
    const float* att_g  = (const float*)d_in[16];
    const float* att_bt = (const float*)d_in[17];
    const float* att_W2 = (const float*)d_in[18];
    const float* att_b2 = (const float*)d_in[19];
    const float* out_W  = (const float*)d_in[20];
    const float* out_b  = (const float*)d_in[21];
    float* out = (float*)d_out;

    float *p_F, *p_G, *p_ctx, *p_att, *p_zero;
    cudaGetSymbolAddress((void**)&p_F,    g_F);
    cudaGetSymbolAddress((void**)&p_G,    g_G);
    cudaGetSymbolAddress((void**)&p_ctx,  g_ctx);
    cudaGetSymbolAddress((void**)&p_att,  g_att);
    cudaGetSymbolAddress((void**)&p_zero, g_zeros);

    __nv_bfloat16 *stah, *stal, *xh, *xl, *s1h, *s1l, *coh, *col_, *efh, *efl;
    cudaGetSymbolAddress((void**)&stah, g_sta_h); cudaGetSymbolAddress((void**)&stal, g_sta_l);
    cudaGetSymbolAddress((void**)&xh,   g_x_h);   cudaGetSymbolAddress((void**)&xl,   g_x_l);
    cudaGetSymbolAddress((void**)&s1h,  g_s1_h);  cudaGetSymbolAddress((void**)&s1l,  g_s1_l);
    cudaGetSymbolAddress((void**)&coh,  g_co_h);  cudaGetSymbolAddress((void**)&col_, g_co_l);
    cudaGetSymbolAddress((void**)&efh,  g_ef_h);  cudaGetSymbolAddress((void**)&efl,  g_ef_l);

    __nv_bfloat16 *ench, *encl, *toph, *topl, *both, *botl,
                  *ctxh, *ctxl, *atth, *attl, *outh, *outl;
    cudaGetSymbolAddress((void**)&ench, g_enc_h);  cudaGetSymbolAddress((void**)&encl, g_enc_l);
    cudaGetSymbolAddress((void**)&toph, g_wtop_h); cudaGetSymbolAddress((void**)&topl, g_wtop_l);
    cudaGetSymbolAddress((void**)&both, g_wbot_h); cudaGetSymbolAddress((void**)&botl, g_wbot_l);
    cudaGetSymbolAddress((void**)&ctxh, g_ctx_h);  cudaGetSymbolAddress((void**)&ctxl, g_ctx_l);
    cudaGetSymbolAddress((void**)&atth, g_att_h);  cudaGetSymbolAddress((void**)&attl, g_att_l);
    cudaGetSymbolAddress((void**)&outh, g_out_h);  cudaGetSymbolAddress((void**)&outl, g_out_l);

    constexpr int SM256 = 2 * (2 * 128 * 72 * 2 + 2 * 64 * 264 * 2) + 1024;
    constexpr int SM128 = 2 * (2 * 128 * 72 * 2 + 2 * 64 * 136 * 2) + 1024;
    cudaFuncSetAttribute(tc_gemm<256, 250, 256,  0, 0, true,  1>,
                         cudaFuncAttributeMaxDynamicSharedMemorySize, SM256);
    cudaFuncSetAttribute(tc_gemm<256, 250, 256,  0, 2, false, 0>,
                         cudaFuncAttributeMaxDynamicSharedMemorySize, SM256);
    cudaFuncSetAttribute(tc_gemm<256, 250, 256,  0, 0, true,  0>,
                         cudaFuncAttributeMaxDynamicSharedMemorySize, SM256);
    cudaFuncSetAttribute(tc_gemm<128, 100, 256,  0, 1, true,  2>,
                         cudaFuncAttributeMaxDynamicSharedMemorySize, SM128);
    cudaFuncSetAttribute(tc_gemm<256, 250, 1088, 2, 2, false, 0>,
                         cudaFuncAttributeMaxDynamicSharedMemorySize, SM256);

    // --- weight prep (segment-remapped K, hi/lo split) ---
    prep_w<<<(256  * 256 + 255) / 256, 256>>>(enc_W,            250,  250, 256, 256,  ench, encl);
    prep_w<<<(256  * 256 + 255) / 256, 256>>>(core_W,           250,  250, 256, 256,  toph, topl);
    prep_w<<<(256  * 256 + 255) / 256, 256>>>(core_W + 250*250, 250,  250, 256, 256,  both, botl);
    prep_w<<<(256  * 256 + 255) / 256, 256>>>(ctx_W,            250,  250, 256, 256,  ctxh, ctxl);
    prep_w<<<(256  * 128 + 255) / 256, 256>>>(att_W1,           250,  100, 128, 256,  atth, attl);
    prep_w<<<(1088 * 256 + 255) / 256, 256>>>(out_W,            1076, 250, 256, 1088, outh, outl);

    // --- activation input prep ---
    prep_split<<<(BK * 256 + 255) / 256, 256>>>(state, 250, 256, BK, stah, stal);
    prep_split<<<(BK * 576 + 255) / 256, 256>>>(x,     576, 576, BK, xh,   xl);

    // s1 = LN(relu(state @ enc_W + b))  -> bf16 hi/lo
    tc_gemm<256, 250, 256, 0, 0, true, 1><<<BK / 128, 256, SM256>>>(
        stah, stal, nullptr, nullptr, nullptr, nullptr, ench, encl,
        enc_b, enc_g, enc_bt, nullptr, nullptr, nullptr, s1h, s1l, 0);

    // F = s1 @ W_top, G = s1 @ W_bot  (fp32, no bias/act/LN)
    tc_gemm<256, 250, 256, 0, 2, false, 0><<<BK / 128, 256, SM256>>>(
        s1h, s1l, nullptr, nullptr, nullptr, nullptr, toph, topl,
        p_zero, nullptr, nullptr, nullptr, nullptr, p_F, nullptr, nullptr, 256);
    tc_gemm<256, 250, 256, 0, 2, false, 0><<<BK / 128, 256, SM256>>>(
        s1h, s1l, nullptr, nullptr, nullptr, nullptr, both, botl,
        p_zero, nullptr, nullptr, nullptr, nullptr, p_G, nullptr, nullptr, 256);

    // core = LN(relu(F[b,i] + G[b,j] + b)) -> bf16 hi/lo (pairwise combine)
    combine_kernel<<<RR / 8, 256>>>(p_F, p_G, core_b, core_g, core_bt, coh, col_);

    // ctx = LN(relu(core @ ctx_W + b)) -> fp32 (effect consumes)
    tc_gemm<256, 250, 256, 0, 0, true, 0><<<RR / 128, 256, SM256>>>(
        coh, col_, nullptr, nullptr, nullptr, nullptr, ctxh, ctxl,
        ctx_b, ctx_g, ctx_bt, nullptr, nullptr, p_ctx, nullptr, nullptr, H1);

    // att = sigmoid(LN(tanh(core @ att_W1 + b1)) @ att_W2 + b2)
    tc_gemm<128, 100, 256, 0, 1, true, 2><<<RR / 128, 256, SM128>>>(
        coh, col_, nullptr, nullptr, nullptr, nullptr, atth, attl,
        att_b1, att_g, att_bt, att_W2, att_b2, p_att, nullptr, nullptr, 0);

    // eff = 7-way attention-weighted reduction of ctx -> bf16 hi/lo
    effect_kernel<<<BK, 256>>>(p_ctx, p_att, efh, efl);

    // out = concat(s1, eff, x) @ out_W + out_b -> fp32 d_out
    tc_gemm<256, 250, 1088, 2, 2, false, 0><<<BK / 128, 256, SM256>>>(
        s1h, s1l, efh, efl, xh, xl, outh, outl,
        out_b, nullptr, nullptr, nullptr, nullptr, out, nullptr, nullptr, H1);
}

// round 9
// speedup vs baseline: 4.0191x; 1.0077x over previous
#include <cuda_runtime.h>
#include <cuda_bf16.h>
#include <mma.h>
#include <math.h>
#include <stdint.h>

using namespace nvcuda;

// ---------------------------------------------------------------------------
// R-NEM cell on tensor cores (wmma bf16 HMMA; tcgen05 unavailable on the
// harness's compute_103 PTX target). fp32 emulated as bf16 hi/lo 3-term.
// R8: prep kernels merged (1 weight-prep + 1 activation-prep) so ncu's
//     fixed capture window (launch #6) lands on the ctx GEMM; F/G GEMMs
//     merged into one dual-B launch to fill the chip in one wave.
// ---------------------------------------------------------------------------

#define EPS_LN 1e-5f

static constexpr int Bn  = 2048;
static constexpr int Kn  = 8;
static constexpr int BK  = Bn * Kn;          // 16384 entity rows
static constexpr int RR  = BK * (Kn - 1);    // 114688 pair rows
static constexpr int H1  = 250;
static constexpr int Mx  = 576;

// fp32 scratch
__device__ float g_F  [BK * 256];
__device__ float g_G  [BK * 256];
__device__ float g_ctx[RR * H1];
__device__ float g_att[RR];
__device__ float g_zeros[256];               // zero bias for F/G GEMMs

// bf16 hi/lo activations (k-padded, zero-filled pad)
__device__ __nv_bfloat16 g_sta_h[BK * 256], g_sta_l[BK * 256];
__device__ __nv_bfloat16 g_x_h  [BK * 576], g_x_l  [BK * 576];
__device__ __nv_bfloat16 g_s1_h [BK * 256], g_s1_l [BK * 256];
__device__ __nv_bfloat16 g_co_h [RR * 256], g_co_l [RR * 256];
__device__ __nv_bfloat16 g_ef_h [BK * 256], g_ef_l [BK * 256];

// Pre-split weights, [Kpad][NT] row-major; 250-wide K segments padded to 256.
__device__ __nv_bfloat16 g_enc_h [256 * 256],  g_enc_l [256 * 256];
__device__ __nv_bfloat16 g_wtop_h[256 * 256],  g_wtop_l[256 * 256];
__device__ __nv_bfloat16 g_wbot_h[256 * 256],  g_wbot_l[256 * 256];
__device__ __nv_bfloat16 g_ctx_h [256 * 256],  g_ctx_l [256 * 256];
__device__ __nv_bfloat16 g_att_h [256 * 128],  g_att_l [256 * 128];
__device__ __nv_bfloat16 g_out_h [1088 * 256], g_out_l [1088 * 256];

// ---------------- cp.async helpers ----------------
__device__ __forceinline__ void cp16(uint32_t dst, const void* src) {
    asm volatile("cp.async.cg.shared.global [%0], [%1], 16;"
                 :: "r"(dst), "l"(src));
}
#define CP_COMMIT() asm volatile("cp.async.commit_group;" ::: "memory")
#define CP_WAIT1()  asm volatile("cp.async.wait_group 1;" ::: "memory")
#define CP_WAIT0()  asm volatile("cp.async.wait_group 0;" ::: "memory")

__device__ __forceinline__ uint32_t smem_u32(const void* p) {
    uint32_t a;
    asm("{ .reg .u64 t; cvta.to.shared.u64 t, %1; cvt.u32.u64 %0, t; }"
        : "=r"(a) : "l"(p));
    return a;
}

__device__ __forceinline__ float warp_sum32(float v) {
    v += __shfl_xor_sync(0xffffffffu, v, 16);
    v += __shfl_xor_sync(0xffffffffu, v, 8);
    v += __shfl_xor_sync(0xffffffffu, v, 4);
    v += __shfl_xor_sync(0xffffffffu, v, 2);
    v += __shfl_xor_sync(0xffffffffu, v, 1);
    return v;
}

// ---------------- merged weight prep ---------------------------------------
__device__ __forceinline__ void prep_one(
    const float* __restrict__ W, int Ksrc, int N, int NT, int idx,
    __nv_bfloat16* __restrict__ bh, __nv_bfloat16* __restrict__ bl)
{
    int kpad = idx / NT;
    int n    = idx - kpad * NT;
    int ksrc; bool valid;
    if (kpad < 512) {
        int seg = kpad >> 8, w = kpad & 255;
        ksrc = seg * 250 + w;
        valid = (w < 250) && (ksrc < Ksrc);
    } else {
        ksrc = 500 + (kpad - 512);
        valid = ksrc < Ksrc;
    }
    float v = (valid && n < N) ? W[ksrc * N + n] : 0.f;
    __nv_bfloat16 h = __float2bfloat16(v);
    bh[idx] = h;
    bl[idx] = __float2bfloat16(v - __bfloat162float(h));
}

// segments: enc 65536 | top 65536 | bot 65536 | ctxW 65536 | att 32768 | out 278528
__global__ __launch_bounds__(256)
void prep_w_all(const float* __restrict__ enc_W, const float* __restrict__ core_W,
                const float* __restrict__ ctx_W, const float* __restrict__ att_W1,
                const float* __restrict__ out_W,
                __nv_bfloat16* ench, __nv_bfloat16* encl,
                __nv_bfloat16* toph, __nv_bfloat16* topl,
                __nv_bfloat16* both, __nv_bfloat16* botl,
                __nv_bfloat16* ctxh, __nv_bfloat16* ctxl,
                __nv_bfloat16* atth, __nv_bfloat16* attl,
                __nv_bfloat16* outh, __nv_bfloat16* outl)
{
    int idx = blockIdx.x * 256 + threadIdx.x;
    if (idx < 65536) {
        prep_one(enc_W, 250, 250, 256, idx, ench, encl);
    } else if (idx < 131072) {
        prep_one(core_W, 250, 250, 256, idx - 65536, toph, topl);
    } else if (idx < 196608) {
        prep_one(core_W + 250 * 250, 250, 250, 256, idx - 131072, both, botl);
    } else if (idx < 262144) {
        prep_one(ctx_W, 250, 250, 256, idx - 196608, ctxh, ctxl);
    } else if (idx < 294912) {
        prep_one(att_W1, 250, 100, 128, idx - 262144, atth, attl);
    } else if (idx < 573440) {
        prep_one(out_W, 1076, 250, 256, idx - 294912, outh, outl);
    }
}

// merged activation prep: state (BK x 250 -> 256) | x (BK x 576)
__global__ __launch_bounds__(256)
void prep_act(const float* __restrict__ state, const float* __restrict__ x,
              __nv_bfloat16* stah, __nv_bfloat16* stal,
              __nv_bfloat16* xh,   __nv_bfloat16* xl)
{
    int idx = blockIdx.x * 256 + threadIdx.x;
    const int NS = BK * 256;
    float v; __nv_bfloat16* ph; __nv_bfloat16* pl; int o;
    if (idx < NS) {
        int r = idx >> 8, c = idx & 255;
        v = (c < 250) ? state[(size_t)r * 250 + c] : 0.f;
        ph = stah; pl = stal; o = idx;
    } else {
        int j = idx - NS;
        if (j >= BK * 576) return;
        v = x[j];
        ph = xh; pl = xl; o = j;
    }
    __nv_bfloat16 h = __float2bfloat16(v);
    ph[o] = h;
    pl[o] = __float2bfloat16(v - __bfloat162float(h));
}

// ---------------- pair combine: core = LN(relu(F[b,i]+G[b,j]+b)) -----------
__global__ __launch_bounds__(256)
void combine_kernel(const float* __restrict__ F, const float* __restrict__ G,
                    const float* __restrict__ bias,
                    const float* __restrict__ gamma,
                    const float* __restrict__ beta,
                    __nv_bfloat16* __restrict__ coh,
                    __nv_bfloat16* __restrict__ col_)
{
    const int r    = blockIdx.x * 8 + (threadIdx.x >> 5);
    const int lane = threadIdx.x & 31;

    int bidx = r / (Kn * (Kn - 1));
    int rem  = r - bidx * (Kn * (Kn - 1));
    int i    = rem / (Kn - 1);
    int jj   = rem - i * (Kn - 1);
    int j    = jj + (jj >= i ? 1 : 0);

    const float* fr = F + (size_t)(bidx * Kn + i) * 256 + lane * 8;
    const float* gr = G + (size_t)(bidx * Kn + j) * 256 + lane * 8;

    float4 f0 = *(const float4*)(fr);
    float4 f1 = *(const float4*)(fr + 4);
    float4 g0 = *(const float4*)(gr);
    float4 g1 = *(const float4*)(gr + 4);

    float v[8];
    {
        const float* fa = &f0.x; const float* ga = &g0.x;
        #pragma unroll
        for (int t = 0; t < 4; ++t) {
            int c = lane * 8 + t;
            v[t] = (c < H1) ? fmaxf(fa[t] + ga[t] + bias[c], 0.f) : 0.f;
        }
        const float* fb = &f1.x; const float* gb = &g1.x;
        #pragma unroll
        for (int t = 0; t < 4; ++t) {
            int c = lane * 8 + 4 + t;
            v[4 + t] = (c < H1) ? fmaxf(fb[t] + gb[t] + bias[c], 0.f) : 0.f;
        }
    }

    float sum = 0.f, ssq = 0.f;
    #pragma unroll
    for (int t = 0; t < 8; ++t) { sum += v[t]; ssq += v[t] * v[t]; }
    sum = warp_sum32(sum);
    ssq = warp_sum32(ssq);
    float mu  = sum / (float)H1;
    float inv = rsqrtf(ssq / (float)H1 - mu * mu + EPS_LN);

    size_t o = (size_t)r * 256 + lane * 8;
    #pragma unroll
    for (int t = 0; t < 8; t += 2) {
        int c0 = lane * 8 + t, c1 = c0 + 1;
        float y0 = (c0 < H1) ? (v[t]     - mu) * inv * gamma[c0] + beta[c0] : 0.f;
        float y1 = (c1 < H1) ? (v[t + 1] - mu) * inv * gamma[c1] + beta[c1] : 0.f;
        __nv_bfloat16 h0 = __float2bfloat16(y0);
        __nv_bfloat16 h1 = __float2bfloat16(y1);
        __nv_bfloat16 l0 = __float2bfloat16(y0 - __bfloat162float(h0));
        __nv_bfloat16 l1 = __float2bfloat16(y1 - __bfloat162float(h1));
        *(__nv_bfloat162*)(coh  + o + t) = __nv_bfloat162(h0, h1);
        *(__nv_bfloat162*)(col_ + o + t) = __nv_bfloat162(l0, l1);
    }
}

// ---------------- fused wmma GEMM ------------------------------------------
// NT: padded N (256 / 128). N: logical cols. KDIM: padded K (mult of 64).
// ASRC: 0 direct (src width = KDIM), 2 tri-concat (s1 256 | eff 256 | x 576).
// ACT: 0 relu, 1 tanh, 2 none.
// OUT: 0 fp32 C, 1 bf16 hi/lo (width NT), 2 attention scalar.
// DUAL: grid doubled; second half of blocks uses B2h/B2l -> Cf2.
template <int NT, int N, int KDIM, int ASRC, int ACT, bool DO_LN, int OUT, bool DUAL>
__global__ __launch_bounds__(256, 1)
void tc_gemm(const __nv_bfloat16* __restrict__ Ah, const __nv_bfloat16* __restrict__ Al,
             const __nv_bfloat16* __restrict__ A2h, const __nv_bfloat16* __restrict__ A2l,
             const __nv_bfloat16* __restrict__ A3h, const __nv_bfloat16* __restrict__ A3l,
             const __nv_bfloat16* __restrict__ Bh0, const __nv_bfloat16* __restrict__ Bl0,
             const __nv_bfloat16* __restrict__ B2h, const __nv_bfloat16* __restrict__ B2l,
             const float* __restrict__ bias, const float* __restrict__ gamma,
             const float* __restrict__ beta, const float* __restrict__ W2,
             const float* __restrict__ b2,
             float* __restrict__ Cf0, float* __restrict__ Cf2,
             __nv_bfloat16* __restrict__ Ch, __nv_bfloat16* __restrict__ Cl, int ldc)
{
    constexpr int KC   = KDIM / 64;
    constexpr int LDA  = 72;                 // elems (144B rows: bank rotation)
    constexpr int LDB  = NT + 8;
    constexpr int CLD  = NT + 8;
    constexpr int A_BYTES = 128 * LDA * 2;
    constexpr int B_BYTES = 64 * LDB * 2;
    constexpr int STG  = 2 * A_BYTES + 2 * B_BYTES;
    constexpr int WN   = NT / 64;
    constexpr int WM   = 8 / WN;
    constexpr int MROW = 128 / WM;
    constexpr int MF   = MROW / 16;
    constexpr int NF   = 4;

    extern __shared__ char smem[];
    const uint32_t sb = smem_u32(smem);

    const int tid = threadIdx.x;
    const int wid = tid >> 5;

    int blk = blockIdx.x;
    bool second = false;
    if (DUAL) {
        const int half = (int)gridDim.x >> 1;
        second = blk >= half;
        if (second) blk -= half;
    }
    const int rowBase = blk * 128;
    const __nv_bfloat16* Bh = (DUAL && second) ? B2h : Bh0;
    const __nv_bfloat16* Bl = (DUAL && second) ? B2l : Bl0;
    float* Cf = (DUAL && second) ? Cf2 : Cf0;

    // ---- async stage of one 64-k chunk (A h/l + B h/l, pure 16B copies) ----
    auto stage = [&](int c) {
        const int st = c & 1;
        const uint32_t ah = sb + st * STG;
        const uint32_t al = ah + A_BYTES;
        const uint32_t bh = al + A_BYTES;
        const uint32_t bl = bh + B_BYTES;
        #pragma unroll
        for (int i = 0; i < 4; ++i) {              // 1024 A-units per matrix
            int u   = tid + i * 256;
            int row = u >> 3, k16 = u & 7;
            const __nv_bfloat16 *sh, *sl;
            int off;
            size_t r = (size_t)(rowBase + row);
            if (ASRC == 0) {
                sh = Ah + r * KDIM; sl = Al + r * KDIM;
                off = c * 64 + k16 * 8;
            } else {
                if (c < 4)      { sh = Ah  + r * 256; sl = Al  + r * 256; off = c * 64 + k16 * 8; }
                else if (c < 8) { sh = A2h + r * 256; sl = A2l + r * 256; off = (c - 4) * 64 + k16 * 8; }
                else            { sh = A3h + r * 576; sl = A3l + r * 576; off = (c - 8) * 64 + k16 * 8; }
            }
            uint32_t d = (uint32_t)(row * (LDA * 2) + k16 * 16);
            cp16(ah + d, sh + off);
            cp16(al + d, sl + off);
        }
        #pragma unroll
        for (int i = 0; i < NT / 32; ++i) {
            int u   = tid + i * 256;
            int kk  = u / (NT / 8), n16 = u % (NT / 8);
            size_t go = (size_t)(c * 64 + kk) * NT + n16 * 8;
            uint32_t d = (uint32_t)(kk * (LDB * 2) + n16 * 16);
            cp16(bh + d, Bh + go);
            cp16(bl + d, Bl + go);
        }
    };

    const int wm = wid / WN, wn = wid % WN;
    const int mrow0 = wm * MROW, ncol0 = wn * 64;

    wmma::fragment<wmma::accumulator, 16, 16, 16, float> acc[MF][NF];
    #pragma unroll
    for (int i = 0; i < MF; ++i)
        #pragma unroll
        for (int j = 0; j < NF; ++j)
            wmma::fill_fragment(acc[i][j], 0.f);

    stage(0); CP_COMMIT();

    for (int c = 0; c < KC; ++c) {
        if (c + 1 < KC) { stage(c + 1); CP_COMMIT(); CP_WAIT1(); }
        else            { CP_WAIT0(); }
        __syncthreads();

        const int st = c & 1;
        const __nv_bfloat16* Ash = (const __nv_bfloat16*)(smem + st * STG);
        const __nv_bfloat16* Asl = Ash + 128 * LDA;
        const __nv_bfloat16* Bsh = Asl + 128 * LDA;
        const __nv_bfloat16* Bsl = Bsh + 64 * LDB;

        #pragma unroll
        for (int s = 0; s < 4; ++s) {
            wmma::fragment<wmma::matrix_a, 16, 16, 16, __nv_bfloat16, wmma::row_major> ah[MF], al[MF];
            #pragma unroll
            for (int i = 0; i < MF; ++i) {
                wmma::load_matrix_sync(ah[i], Ash + (mrow0 + i * 16) * LDA + s * 16, LDA);
                wmma::load_matrix_sync(al[i], Asl + (mrow0 + i * 16) * LDA + s * 16, LDA);
            }
            #pragma unroll
            for (int j = 0; j < NF; ++j) {
                wmma::fragment<wmma::matrix_b, 16, 16, 16, __nv_bfloat16, wmma::row_major> bh, bl;
                wmma::load_matrix_sync(bh, Bsh + (s * 16) * LDB + ncol0 + j * 16, LDB);
                wmma::load_matrix_sync(bl, Bsl + (s * 16) * LDB + ncol0 + j * 16, LDB);
                #pragma unroll
                for (int i = 0; i < MF; ++i) {
                    wmma::mma_sync(acc[i][j], ah[i], bh, acc[i][j]);
                    wmma::mma_sync(acc[i][j], ah[i], bl, acc[i][j]);
                    wmma::mma_sync(acc[i][j], al[i], bh, acc[i][j]);
                }
            }
        }
        __syncthreads();
    }

    // ---- dump accumulators to SMEM fp32 ----
    float* Cs = (float*)smem;
    #pragma unroll
    for (int i = 0; i < MF; ++i)
        #pragma unroll
        for (int j = 0; j < NF; ++j)
            wmma::store_matrix_sync(Cs + (mrow0 + i * 16) * CLD + ncol0 + j * 16,
                                    acc[i][j], CLD, wmma::mem_row_major);
    __syncthreads();

    constexpr int HC = NT / 2;
    float* muS  = (float*)(smem + 128 * CLD * 4);
    float* invS = muS + 128;

    if constexpr (OUT == 2) {
        const int row = tid >> 1, hf = tid & 1;
        const float* crow = Cs + row * CLD + hf * HC;
        float sum = 0.f, ssq = 0.f;
        #pragma unroll 4
        for (int j = 0; j < HC; ++j) {
            int cc = hf * HC + j;
            float v = 0.f;
            if (cc < N) { v = tanhf(crow[j] + bias[cc]); }
            sum += v; ssq += v * v;
        }
        float s = sum + __shfl_xor_sync(0xffffffffu, sum, 1);
        float q = ssq + __shfl_xor_sync(0xffffffffu, ssq, 1);
        float mu = s / (float)N;
        float inv = rsqrtf(q / (float)N - mu * mu + EPS_LN);
        float d = 0.f;
        #pragma unroll 4
        for (int j = 0; j < HC; ++j) {
            int cc = hf * HC + j;
            if (cc < N) {
                float v = tanhf(crow[j] + bias[cc]);
                v = (v - mu) * inv * gamma[cc] + beta[cc];
                d += v * W2[cc];
            }
        }
        d += __shfl_xor_sync(0xffffffffu, d, 1);
        if (hf == 0) {
            float z = d + b2[0];
            Cf[rowBase + row] = 1.f / (1.f + expf(-z));
        }
    } else {
        if constexpr (DO_LN) {
            const int row = tid >> 1, hf = tid & 1;
            const float* crow = Cs + row * CLD + hf * HC;
            float sum = 0.f, ssq = 0.f;
            #pragma unroll 4
            for (int j = 0; j < HC; ++j) {
                int cc = hf * HC + j;
                float v = 0.f;
                if (cc < N) {
                    v = crow[j] + bias[cc];
                    if (ACT == 0)      v = fmaxf(v, 0.f);
                    else if (ACT == 1) v = tanhf(v);
                }
                sum += v; ssq += v * v;
            }
            float s = sum + __shfl_xor_sync(0xffffffffu, sum, 1);
            float q = ssq + __shfl_xor_sync(0xffffffffu, ssq, 1);
            if (hf == 0) {
                float mu = s / (float)N;
                muS[row]  = mu;
                invS[row] = rsqrtf(q / (float)N - mu * mu + EPS_LN);
            }
            __syncthreads();
        }
        for (int e = tid * 2; e < 128 * NT; e += 512) {
            int row = e / NT;
            int col = e - row * NT;
            float mu = 0.f, iv = 0.f;
            if (DO_LN) { mu = muS[row]; iv = invS[row]; }
            float v[2];
            #pragma unroll
            for (int t = 0; t < 2; ++t) {
                int cc = col + t;
                float xv = 0.f;
                if (cc < N) {
                    xv = Cs[row * CLD + cc] + bias[cc];
                    if (ACT == 0)      xv = fmaxf(xv, 0.f);
                    else if (ACT == 1) xv = tanhf(xv);
                    if (DO_LN)
                        xv = (xv - mu) * iv * gamma[cc] + beta[cc];
                }
                v[t] = xv;
            }
            if (OUT == 1) {
                __nv_bfloat16 h0 = __float2bfloat16(v[0]);
                __nv_bfloat16 h1 = __float2bfloat16(v[1]);
                __nv_bfloat16 l0 = __float2bfloat16(v[0] - __bfloat162float(h0));
                __nv_bfloat16 l1 = __float2bfloat16(v[1] - __bfloat162float(h1));
                size_t o = (size_t)(rowBase + row) * NT + col;
                *(__nv_bfloat162*)(Ch + o) = __nv_bfloat162(h0, h1);
                *(__nv_bfloat162*)(Cl + o) = __nv_bfloat162(l0, l1);
            } else {
                size_t o = (size_t)(rowBase + row) * ldc + col;
                if (col < N)     Cf[o]     = v[0];
                if (col + 1 < N) Cf[o + 1] = v[1];
            }
        }
    }
}

// eff[bk, c] = sum_{j<7} ctx[bk*7+j, c] * att[bk*7+j]; emit bf16 hi/lo pad-256
__global__ __launch_bounds__(256)
void effect_kernel(const float* __restrict__ ctx,
                   const float* __restrict__ att,
                   __nv_bfloat16* __restrict__ effh,
                   __nv_bfloat16* __restrict__ effl)
{
    const int bk = blockIdx.x;
    __shared__ float a[Kn - 1];
    if (threadIdx.x < Kn - 1) a[threadIdx.x] = att[bk * (Kn - 1) + threadIdx.x];
    __syncthreads();
    int c = threadIdx.x;
    float s = 0.f;
    if (c < H1) {
        const float* base = ctx + (size_t)bk * (Kn - 1) * H1;
        #pragma unroll
        for (int j = 0; j < Kn - 1; ++j)
            s = fmaf(base[j * H1 + c], a[j], s);
    }
    __nv_bfloat16 h = __float2bfloat16(s);
    effh[(size_t)bk * 256 + c] = h;
    effl[(size_t)bk * 256 + c] = __float2bfloat16(s - __bfloat162float(h));
}

extern "C" void kernel_launch(void* const* d_in, const int* in_sizes, int n_in,
                              void* d_out, int out_size)
{
    const float* x      = (const float*)d_in[0];
    const float* state  = (const float*)d_in[1];
    const float* enc_W  = (const float*)d_in[2];
    const float* enc_b  = (const float*)d_in[3];
    const float* enc_g  = (const float*)d_in[4];
    const float* enc_bt = (const float*)d_in[5];
    const float* core_W = (const float*)d_in[6];
    const float* core_b = (const float*)d_in[7];
    const float* core_g = (const float*)d_in[8];
    const float* core_bt= (const float*)d_in[9];
    const float* ctx_W  = (const float*)d_in[10];
    const float* ctx_b  = (const float*)d_in[11];
    const float* ctx_g  = (const float*)d_in[12];
    const float* ctx_bt = (const float*)d_in[13];
    const float* att_W1 = (const float*)d_in[14];
    const float* att_b1 = (const float*)d_in[15];
    const float* att_g  = (const float*)d_in[16];
    const float* att_bt = (const float*)d_in[17];
    const float* att_W2 = (const float*)d_in[18];
    const float* att_b2 = (const float*)d_in[19];
    const float* out_W  = (const float*)d_in[20];
    const float* out_b  = (const float*)d_in[21];
    float* out = (float*)d_out;

    float *p_F, *p_G, *p_ctx, *p_att, *p_zero;
    cudaGetSymbolAddress((void**)&p_F,    g_F);
    cudaGetSymbolAddress((void**)&p_G,    g_G);
    cudaGetSymbolAddress((void**)&p_ctx,  g_ctx);
    cudaGetSymbolAddress((void**)&p_att,  g_att);
    cudaGetSymbolAddress((void**)&p_zero, g_zeros);

    __nv_bfloat16 *stah, *stal, *xh, *xl, *s1h, *s1l, *coh, *col_, *efh, *efl;
    cudaGetSymbolAddress((void**)&stah, g_sta_h); cudaGetSymbolAddress((void**)&stal, g_sta_l);
    cudaGetSymbolAddress((void**)&xh,   g_x_h);   cudaGetSymbolAddress((void**)&xl,   g_x_l);
    cudaGetSymbolAddress((void**)&s1h,  g_s1_h);  cudaGetSymbolAddress((void**)&s1l,  g_s1_l);
    cudaGetSymbolAddress((void**)&coh,  g_co_h);  cudaGetSymbolAddress((void**)&col_, g_co_l);
    cudaGetSymbolAddress((void**)&efh,  g_ef_h);  cudaGetSymbolAddress((void**)&efl,  g_ef_l);

    __nv_bfloat16 *ench, *encl, *toph, *topl, *both, *botl,
                  *ctxh, *ctxl, *atth, *attl, *outh, *outl;
    cudaGetSymbolAddress((void**)&ench, g_enc_h);  cudaGetSymbolAddress((void**)&encl, g_enc_l);
    cudaGetSymbolAddress((void**)&toph, g_wtop_h); cudaGetSymbolAddress((void**)&topl, g_wtop_l);
    cudaGetSymbolAddress((void**)&both, g_wbot_h); cudaGetSymbolAddress((void**)&botl, g_wbot_l);
    cudaGetSymbolAddress((void**)&ctxh, g_ctx_h);  cudaGetSymbolAddress((void**)&ctxl, g_ctx_l);
    cudaGetSymbolAddress((void**)&atth, g_att_h);  cudaGetSymbolAddress((void**)&attl, g_att_l);
    cudaGetSymbolAddress((void**)&outh, g_out_h);  cudaGetSymbolAddress((void**)&outl, g_out_l);

    constexpr int SM256 = 2 * (2 * 128 * 72 * 2 + 2 * 64 * 264 * 2) + 1024;
    constexpr int SM128 = 2 * (2 * 128 * 72 * 2 + 2 * 64 * 136 * 2) + 1024;
    cudaFuncSetAttribute(tc_gemm<256, 250, 256,  0, 0, true,  1, false>,
                         cudaFuncAttributeMaxDynamicSharedMemorySize, SM256);
    cudaFuncSetAttribute(tc_gemm<256, 250, 256,  0, 2, false, 0, true>,
                         cudaFuncAttributeMaxDynamicSharedMemorySize, SM256);
    cudaFuncSetAttribute(tc_gemm<256, 250, 256,  0, 0, true,  0, false>,
                         cudaFuncAttributeMaxDynamicSharedMemorySize, SM256);
    cudaFuncSetAttribute(tc_gemm<128, 100, 256,  0, 1, true,  2, false>,
                         cudaFuncAttributeMaxDynamicSharedMemorySize, SM128);
    cudaFuncSetAttribute(tc_gemm<256, 250, 1088, 2, 2, false, 0, false>,
                         cudaFuncAttributeMaxDynamicSharedMemorySize, SM256);

    // #1: all weight prep (573440 items)
    prep_w_all<<<(573440 + 255) / 256, 256>>>(
        enc_W, core_W, ctx_W, att_W1, out_W,
        ench, encl, toph, topl, both, botl, ctxh, ctxl, atth, attl, outh, outl);

    // #2: activation prep (state + x)
    prep_act<<<(BK * 256 + BK * 576 + 255) / 256, 256>>>(state, x, stah, stal, xh, xl);

    // #3: s1 = LN(relu(state @ enc_W + b)) -> bf16 hi/lo
    tc_gemm<256, 250, 256, 0, 0, true, 1, false><<<BK / 128, 256, SM256>>>(
        stah, stal, nullptr, nullptr, nullptr, nullptr, ench, encl, nullptr, nullptr,
        enc_b, enc_g, enc_bt, nullptr, nullptr, nullptr, nullptr, s1h, s1l, 0);

    // #4: F = s1 @ W_top AND G = s1 @ W_bot (dual-B, one full-chip launch)
    tc_gemm<256, 250, 256, 0, 2, false, 0, true><<<2 * (BK / 128), 256, SM256>>>(
        s1h, s1l, nullptr, nullptr, nullptr, nullptr, toph, topl, both, botl,
        p_zero, nullptr, nullptr, nullptr, nullptr, p_F, p_G, nullptr, nullptr, 256);

    // #5: core = LN(relu(F[b,i] + G[b,j] + b)) -> bf16 hi/lo
    combine_kernel<<<RR / 8, 256>>>(p_F, p_G, core_b, core_g, core_bt, coh, col_);

    // #6 (ncu capture window): ctx = LN(relu(core @ ctx_W + b)) -> fp32
    tc_gemm<256, 250, 256, 0, 0, true, 0, false><<<RR / 128, 256, SM256>>>(
        coh, col_, nullptr, nullptr, nullptr, nullptr, ctxh, ctxl, nullptr, nullptr,
        ctx_b, ctx_g, ctx_bt, nullptr, nullptr, p_ctx, nullptr, nullptr, nullptr, H1);

    // #7: att = sigmoid(LN(tanh(core @ att_W1 + b1)) @ att_W2 + b2)
    tc_gemm<128, 100, 256, 0, 1, true, 2, false><<<RR / 128, 256, SM128>>>(
        coh, col_, nullptr, nullptr, nullptr, nullptr, atth, attl, nullptr, nullptr,
        att_b1, att_g, att_bt, att_W2, att_b2, p_att, nullptr, nullptr, nullptr, 0);

    // #8: eff = 7-way attention-weighted reduction of ctx -> bf16 hi/lo
    effect_kernel<<<BK, 256>>>(p_ctx, p_att, efh, efl);

    // #9: out = concat(s1, eff, x) @ out_W + out_b -> fp32 d_out
    tc_gemm<256, 250, 1088, 2, 2, false, 0, false><<<BK / 128, 256, SM256>>>(
        s1h, s1l, efh, efl, xh, xl, outh, outl, nullptr, nullptr,
        out_b, nullptr, nullptr, nullptr, nullptr, out, nullptr, nullptr, nullptr, H1);
}